// round 1
// baseline (speedup 1.0000x reference)
#include <cuda_runtime.h>
#include <cstdint>

// ---------------------------------------------------------------------------
// LSTM attention cell, B=4096, E=H=C=1024, D=3072, all fp32.
//   gates: i,f,o = sigmoid(combined @ W.T + b), g = tanh(...)
//   cell = f*c_prev + i*g ; hidden = o*tanh(cell)
//   resid = emb + hidden@Wh.T + bh + ctx@Wc.T + bc
//   pred  = resid@Wp.T + bp
// Output layout (tuple order): [prediction B*E | hidden B*H | cell B*H]
// ---------------------------------------------------------------------------

#define BM 128
#define BN 128
#define BK 16
#define MDIM 4096
#define NDIM 1024
#define KSEG 1024   // every K segment (E, H, C) is 1024 wide

static const size_t BH = 4096ull * 1024ull;   // B*H == B*E

// Scratch (static device allocation — no runtime allocs allowed)
__device__ float g_gates[4ull * 4096ull * 1024ull];   // i,f,o,g pre-activated values (post-activation actually)
__device__ float g_resid[4096ull * 1024ull];

// ---------------------------------------------------------------------------
// packed f32x2 helpers (ptxas never auto-emits FFMA2; PTX-only path)
// ---------------------------------------------------------------------------
__device__ __forceinline__ unsigned long long pack2(float x, float y) {
    unsigned long long r;
    asm("mov.b64 %0, {%1, %2};" : "=l"(r) : "f"(x), "f"(y));
    return r;
}
__device__ __forceinline__ void fma2(unsigned long long& d,
                                     unsigned long long a,
                                     unsigned long long b) {
    asm("fma.rn.f32x2 %0, %1, %2, %0;" : "+l"(d) : "l"(a), "l"(b));
}
__device__ __forceinline__ float2 unpack2(unsigned long long v) {
    float2 r;
    asm("mov.b64 {%0, %1}, %2;" : "=f"(r.x), "=f"(r.y) : "l"(v));
    return r;
}

__device__ __forceinline__ float sigmoidf_fast(float x) {
    return 1.0f / (1.0f + __expf(-x));
}

// ---------------------------------------------------------------------------
// Shared GEMM core: out[M,N] tile accum of  A @ W^T
//   A = concat_k of nseg matrices, each [MDIM, 1024] row-major (stride 1024)
//   W = concat_k of nseg matrices, each [NDIM, 1024] with row stride wstride
// Accumulates into acc2[8][4] packed-f32x2:
//   acc2[i][0..1] -> columns nA..nA+3 ; acc2[i][2..3] -> columns nB..nB+3
// ---------------------------------------------------------------------------
struct TileCtx {
    int m0, nA, nB;       // offsets inside the 128x128 block tile
    long bm, bn;          // block-tile global offsets
};

__device__ __forceinline__ void gemm_core(
    const float* const* Aseg, const float* const* Wseg,
    int nseg, int wstride,
    unsigned long long acc2[8][4], TileCtx& tc)
{
    __shared__ float As[BK][BM];
    __shared__ float Bs[BK][BN];

    const int tid  = threadIdx.x;
    const int warp = tid >> 5, lane = tid & 31;
    const int wm = warp >> 1, wn = warp & 1;     // 4 x 2 warps
    const int lm = lane >> 3, ln = lane & 7;     // 4 x 8 lanes
    tc.m0 = wm * 32 + lm * 8;
    tc.nA = wn * 64 + ln * 4;
    tc.nB = tc.nA + 32;
    tc.bm = (long)blockIdx.x * BM;
    tc.bn = (long)blockIdx.y * BN;

    const int KT = nseg * (KSEG / BK);           // k-tiles

    // per-thread load coordinates: 2 x float4 for each of A and W per k-tile
    const int row0 = tid >> 2;                   // 0..63
    const int c4   = (tid & 3) * 4;              // 0,4,8,12

    for (int kt = 0; kt < KT; ++kt) {
        const int seg = kt >> 6;                 // 1024/16 = 64 tiles per segment
        const int ko  = (kt & 63) * BK;
        const float* Ab = Aseg[seg] + tc.bm * KSEG + ko;
        const float* Wb = Wseg[seg] + tc.bn * (long)wstride + ko;

        #pragma unroll
        for (int i = 0; i < 2; ++i) {
            const int row = row0 + i * 64;
            float4 va = *(const float4*)(Ab + (long)row * KSEG + c4);
            As[c4 + 0][row] = va.x; As[c4 + 1][row] = va.y;
            As[c4 + 2][row] = va.z; As[c4 + 3][row] = va.w;
            float4 vb = *(const float4*)(Wb + (long)row * wstride + c4);
            Bs[c4 + 0][row] = vb.x; Bs[c4 + 1][row] = vb.y;
            Bs[c4 + 2][row] = vb.z; Bs[c4 + 3][row] = vb.w;
        }
        __syncthreads();

        #pragma unroll
        for (int k = 0; k < BK; ++k) {
            float4 a0 = *(const float4*)&As[k][tc.m0];
            float4 a1 = *(const float4*)&As[k][tc.m0 + 4];
            float4 b0 = *(const float4*)&Bs[k][tc.nA];
            float4 b1 = *(const float4*)&Bs[k][tc.nB];
            unsigned long long bb0 = pack2(b0.x, b0.y);
            unsigned long long bb1 = pack2(b0.z, b0.w);
            unsigned long long bb2 = pack2(b1.x, b1.y);
            unsigned long long bb3 = pack2(b1.z, b1.w);
            float af[8] = {a0.x, a0.y, a0.z, a0.w, a1.x, a1.y, a1.z, a1.w};
            #pragma unroll
            for (int i = 0; i < 8; ++i) {
                unsigned long long ai = pack2(af[i], af[i]);
                fma2(acc2[i][0], ai, bb0);
                fma2(acc2[i][1], ai, bb1);
                fma2(acc2[i][2], ai, bb2);
                fma2(acc2[i][3], ai, bb3);
            }
        }
        __syncthreads();
    }
}

// ---------------------------------------------------------------------------
// Kernel 1: 4 gate GEMMs fused (gridDim.z selects gate). K = 3072.
//   gate 0..2 -> sigmoid, gate 3 -> tanh. Writes g_gates[gate].
// ---------------------------------------------------------------------------
__global__ void __launch_bounds__(256, 2)
gates_kernel(const float* __restrict__ emb, const float* __restrict__ hid,
             const float* __restrict__ ctx,
             const float* __restrict__ Wi, const float* __restrict__ Wf,
             const float* __restrict__ Wo, const float* __restrict__ Wg,
             const float* __restrict__ bi, const float* __restrict__ bf,
             const float* __restrict__ bo, const float* __restrict__ bg)
{
    const int gate = blockIdx.z;
    const float* Wsel = (gate == 0) ? Wi : (gate == 1) ? Wf : (gate == 2) ? Wo : Wg;
    const float* bsel = (gate == 0) ? bi : (gate == 1) ? bf : (gate == 2) ? bo : bg;

    const float* Aseg[3] = {emb, hid, ctx};
    const float* Wseg[3] = {Wsel, Wsel + 1024, Wsel + 2048};  // row stride 3072

    unsigned long long acc2[8][4];
    #pragma unroll
    for (int i = 0; i < 8; ++i)
        #pragma unroll
        for (int j = 0; j < 4; ++j) acc2[i][j] = 0ull;

    TileCtx tc;
    gemm_core(Aseg, Wseg, 3, 3072, acc2, tc);

    float* out = g_gates + (size_t)gate * BH;
    #pragma unroll
    for (int i = 0; i < 8; ++i) {
        const long m = tc.bm + tc.m0 + i;
        float* orow = out + m * NDIM;
        #pragma unroll
        for (int half = 0; half < 2; ++half) {
            const long col = tc.bn + (half == 0 ? tc.nA : tc.nB);
            float2 v0 = unpack2(acc2[i][half * 2 + 0]);
            float2 v1 = unpack2(acc2[i][half * 2 + 1]);
            float4 r;
            r.x = v0.x + bsel[col + 0];
            r.y = v0.y + bsel[col + 1];
            r.z = v1.x + bsel[col + 2];
            r.w = v1.y + bsel[col + 3];
            if (gate < 3) {
                r.x = sigmoidf_fast(r.x); r.y = sigmoidf_fast(r.y);
                r.z = sigmoidf_fast(r.z); r.w = sigmoidf_fast(r.w);
            } else {
                r.x = tanhf(r.x); r.y = tanhf(r.y);
                r.z = tanhf(r.z); r.w = tanhf(r.w);
            }
            *(float4*)(orow + col) = r;
        }
    }
}

// ---------------------------------------------------------------------------
// Kernel 2: cell = f*c_prev + i*g ; hidden = o*tanh(cell)
//   writes hidden -> out[BH .. 2BH), cell -> out[2BH .. 3BH)
// ---------------------------------------------------------------------------
__global__ void cellhid_kernel(const float* __restrict__ cprev,
                               float* __restrict__ out)
{
    const size_t i = ((size_t)blockIdx.x * blockDim.x + threadIdx.x) * 4;
    float4 gi = *(const float4*)&g_gates[i];
    float4 gf = *(const float4*)&g_gates[BH + i];
    float4 go = *(const float4*)&g_gates[2 * BH + i];
    float4 gg = *(const float4*)&g_gates[3 * BH + i];
    float4 cp = *(const float4*)&cprev[i];
    float4 c, h;
    c.x = gf.x * cp.x + gi.x * gg.x;  h.x = go.x * tanhf(c.x);
    c.y = gf.y * cp.y + gi.y * gg.y;  h.y = go.y * tanhf(c.y);
    c.z = gf.z * cp.z + gi.z * gg.z;  h.z = go.z * tanhf(c.z);
    c.w = gf.w * cp.w + gi.w * gg.w;  h.w = go.w * tanhf(c.w);
    *(float4*)&out[BH + i]     = h;
    *(float4*)&out[2 * BH + i] = c;
}

// ---------------------------------------------------------------------------
// Kernel 3/4: generic GEMM  out = [addend +] A@W^T + bias0 [+ bias1]
//   up to 2 K-segments (each 1024), W row stride = wstride
// ---------------------------------------------------------------------------
__global__ void __launch_bounds__(256, 2)
gemm_kernel(const float* __restrict__ A0, const float* __restrict__ A1,
            const float* __restrict__ W0, const float* __restrict__ W1,
            int nseg, int wstride,
            const float* __restrict__ bias0, const float* __restrict__ bias1,
            const float* __restrict__ addend,
            float* __restrict__ out)
{
    const float* Aseg[3] = {A0, A1, nullptr};
    const float* Wseg[3] = {W0, W1, nullptr};

    unsigned long long acc2[8][4];
    #pragma unroll
    for (int i = 0; i < 8; ++i)
        #pragma unroll
        for (int j = 0; j < 4; ++j) acc2[i][j] = 0ull;

    TileCtx tc;
    gemm_core(Aseg, Wseg, nseg, wstride, acc2, tc);

    #pragma unroll
    for (int i = 0; i < 8; ++i) {
        const long m = tc.bm + tc.m0 + i;
        float* orow = out + m * NDIM;
        const float* arow = addend ? addend + m * NDIM : nullptr;
        #pragma unroll
        for (int half = 0; half < 2; ++half) {
            const long col = tc.bn + (half == 0 ? tc.nA : tc.nB);
            float2 v0 = unpack2(acc2[i][half * 2 + 0]);
            float2 v1 = unpack2(acc2[i][half * 2 + 1]);
            float4 r = make_float4(v0.x, v0.y, v1.x, v1.y);
            r.x += bias0[col + 0]; r.y += bias0[col + 1];
            r.z += bias0[col + 2]; r.w += bias0[col + 3];
            if (bias1) {
                r.x += bias1[col + 0]; r.y += bias1[col + 1];
                r.z += bias1[col + 2]; r.w += bias1[col + 3];
            }
            if (arow) {
                float4 a = *(const float4*)(arow + col);
                r.x += a.x; r.y += a.y; r.z += a.z; r.w += a.w;
            }
            *(float4*)(orow + col) = r;
        }
    }
}

// ---------------------------------------------------------------------------
// kernel_launch
// ---------------------------------------------------------------------------
extern "C" void kernel_launch(void* const* d_in, const int* in_sizes, int n_in,
                              void* d_out, int out_size)
{
    const float* emb   = (const float*)d_in[0];
    const float* hid   = (const float*)d_in[1];
    const float* cprev = (const float*)d_in[2];
    const float* ctx   = (const float*)d_in[3];
    const float* Wi = (const float*)d_in[4];  const float* bi = (const float*)d_in[5];
    const float* Wf = (const float*)d_in[6];  const float* bf = (const float*)d_in[7];
    const float* Wo = (const float*)d_in[8];  const float* bo = (const float*)d_in[9];
    const float* Wg = (const float*)d_in[10]; const float* bg = (const float*)d_in[11];
    const float* Wc = (const float*)d_in[12]; const float* bc = (const float*)d_in[13];
    const float* Wh = (const float*)d_in[14]; const float* bh = (const float*)d_in[15];
    const float* Wp = (const float*)d_in[16]; const float* bp = (const float*)d_in[17];
    float* out = (float*)d_out;

    static float* resid_ptr = nullptr;
    if (!resid_ptr) {
        cudaGetSymbolAddress((void**)&resid_ptr, g_resid);
    }

    // 1) four gate GEMMs (K=3072), fused epilogue activations -> g_gates
    gates_kernel<<<dim3(MDIM / BM, NDIM / BN, 4), 256>>>(
        emb, hid, ctx, Wi, Wf, Wo, Wg, bi, bf, bo, bg);

    // 2) cell & hidden elementwise -> out[BH..2BH) hidden, out[2BH..3BH) cell
    cellhid_kernel<<<(int)(BH / 4 / 256), 256>>>(cprev, out);

    // 3) resid = emb + hidden@Wh^T + bh + ctx@Wc^T + bc   (K = 2048)
    gemm_kernel<<<dim3(MDIM / BM, NDIM / BN), 256>>>(
        out + BH /*hidden*/, ctx, Wh, Wc, 2, 1024, bh, bc, emb, resid_ptr);

    // 4) prediction = resid@Wp^T + bp -> out[0..BH)
    gemm_kernel<<<dim3(MDIM / BM, NDIM / BN), 256>>>(
        resid_ptr, nullptr, Wp, nullptr, 1, 1024, bp, nullptr, nullptr, out);
}

// round 2
// speedup vs baseline: 1.0050x; 1.0050x over previous
#include <cuda_runtime.h>
#include <cstdint>

// ---------------------------------------------------------------------------
// LSTM attention cell, B=4096, E=H=C=1024, D=3072, all fp32.
//   gates: i,f,o = sigmoid(combined @ W.T + b), g = tanh(...)
//   cell = f*c_prev + i*g ; hidden = o*tanh(cell)
//   resid = emb + hidden@Wh.T + bh + ctx@Wc.T + bc
//   pred  = resid@Wp.T + bp
// Output layout (tuple order): [prediction B*E | hidden B*H | cell B*H]
// ---------------------------------------------------------------------------

#define BM 128
#define BN 128
#define BK 16
#define MDIM 4096
#define NDIM 1024
#define KSEG 1024   // every K segment (E, H, C) is 1024 wide

static const size_t BH = 4096ull * 1024ull;   // B*H == B*E

// Scratch (static device allocation — no runtime allocs allowed)
__device__ float g_gates[4ull * 4096ull * 1024ull];   // i,f,o,g pre-activated values (post-activation actually)
__device__ float g_resid[4096ull * 1024ull];

// ---------------------------------------------------------------------------
// packed f32x2 helpers (ptxas never auto-emits FFMA2; PTX-only path)
// ---------------------------------------------------------------------------
__device__ __forceinline__ unsigned long long pack2(float x, float y) {
    unsigned long long r;
    asm("mov.b64 %0, {%1, %2};" : "=l"(r) : "f"(x), "f"(y));
    return r;
}
__device__ __forceinline__ void fma2(unsigned long long& d,
                                     unsigned long long a,
                                     unsigned long long b) {
    asm("fma.rn.f32x2 %0, %1, %2, %0;" : "+l"(d) : "l"(a), "l"(b));
}
__device__ __forceinline__ float2 unpack2(unsigned long long v) {
    float2 r;
    asm("mov.b64 {%0, %1}, %2;" : "=f"(r.x), "=f"(r.y) : "l"(v));
    return r;
}

__device__ __forceinline__ float sigmoidf_fast(float x) {
    return 1.0f / (1.0f + __expf(-x));
}

// ---------------------------------------------------------------------------
// Shared GEMM core: out[M,N] tile accum of  A @ W^T
//   A = concat_k of nseg matrices, each [MDIM, 1024] row-major (stride 1024)
//   W = concat_k of nseg matrices, each [NDIM, 1024] with row stride wstride
// Accumulates into acc2[8][4] packed-f32x2:
//   acc2[i][0..1] -> columns nA..nA+3 ; acc2[i][2..3] -> columns nB..nB+3
// ---------------------------------------------------------------------------
struct TileCtx {
    int m0, nA, nB;       // offsets inside the 128x128 block tile
    long bm, bn;          // block-tile global offsets
};

__device__ __forceinline__ void gemm_core(
    const float* const* Aseg, const float* const* Wseg,
    int nseg, int wstride,
    unsigned long long acc2[8][4], TileCtx& tc)
{
    __shared__ float As[BK][BM];
    __shared__ float Bs[BK][BN];

    const int tid  = threadIdx.x;
    const int warp = tid >> 5, lane = tid & 31;
    const int wm = warp >> 1, wn = warp & 1;     // 4 x 2 warps
    const int lm = lane >> 3, ln = lane & 7;     // 4 x 8 lanes
    tc.m0 = wm * 32 + lm * 8;
    tc.nA = wn * 64 + ln * 4;
    tc.nB = tc.nA + 32;
    tc.bm = (long)blockIdx.x * BM;
    tc.bn = (long)blockIdx.y * BN;

    const int KT = nseg * (KSEG / BK);           // k-tiles

    // per-thread load coordinates: 2 x float4 for each of A and W per k-tile
    const int row0 = tid >> 2;                   // 0..63
    const int c4   = (tid & 3) * 4;              // 0,4,8,12

    for (int kt = 0; kt < KT; ++kt) {
        const int seg = kt >> 6;                 // 1024/16 = 64 tiles per segment
        const int ko  = (kt & 63) * BK;
        const float* Ab = Aseg[seg] + tc.bm * KSEG + ko;
        const float* Wb = Wseg[seg] + tc.bn * (long)wstride + ko;

        #pragma unroll
        for (int i = 0; i < 2; ++i) {
            const int row = row0 + i * 64;
            float4 va = *(const float4*)(Ab + (long)row * KSEG + c4);
            As[c4 + 0][row] = va.x; As[c4 + 1][row] = va.y;
            As[c4 + 2][row] = va.z; As[c4 + 3][row] = va.w;
            float4 vb = *(const float4*)(Wb + (long)row * wstride + c4);
            Bs[c4 + 0][row] = vb.x; Bs[c4 + 1][row] = vb.y;
            Bs[c4 + 2][row] = vb.z; Bs[c4 + 3][row] = vb.w;
        }
        __syncthreads();

        #pragma unroll
        for (int k = 0; k < BK; ++k) {
            float4 a0 = *(const float4*)&As[k][tc.m0];
            float4 a1 = *(const float4*)&As[k][tc.m0 + 4];
            float4 b0 = *(const float4*)&Bs[k][tc.nA];
            float4 b1 = *(const float4*)&Bs[k][tc.nB];
            unsigned long long bb0 = pack2(b0.x, b0.y);
            unsigned long long bb1 = pack2(b0.z, b0.w);
            unsigned long long bb2 = pack2(b1.x, b1.y);
            unsigned long long bb3 = pack2(b1.z, b1.w);
            float af[8] = {a0.x, a0.y, a0.z, a0.w, a1.x, a1.y, a1.z, a1.w};
            #pragma unroll
            for (int i = 0; i < 8; ++i) {
                unsigned long long ai = pack2(af[i], af[i]);
                fma2(acc2[i][0], ai, bb0);
                fma2(acc2[i][1], ai, bb1);
                fma2(acc2[i][2], ai, bb2);
                fma2(acc2[i][3], ai, bb3);
            }
        }
        __syncthreads();
    }
}

// ---------------------------------------------------------------------------
// Kernel 1: 4 gate GEMMs fused (gridDim.z selects gate). K = 3072.
//   gate 0..2 -> sigmoid, gate 3 -> tanh. Writes g_gates[gate].
// ---------------------------------------------------------------------------
__global__ void __launch_bounds__(256, 2)
gates_kernel(const float* __restrict__ emb, const float* __restrict__ hid,
             const float* __restrict__ ctx,
             const float* __restrict__ Wi, const float* __restrict__ Wf,
             const float* __restrict__ Wo, const float* __restrict__ Wg,
             const float* __restrict__ bi, const float* __restrict__ bf,
             const float* __restrict__ bo, const float* __restrict__ bg)
{
    const int gate = blockIdx.z;
    const float* Wsel = (gate == 0) ? Wi : (gate == 1) ? Wf : (gate == 2) ? Wo : Wg;
    const float* bsel = (gate == 0) ? bi : (gate == 1) ? bf : (gate == 2) ? bo : bg;

    const float* Aseg[3] = {emb, hid, ctx};
    const float* Wseg[3] = {Wsel, Wsel + 1024, Wsel + 2048};  // row stride 3072

    unsigned long long acc2[8][4];
    #pragma unroll
    for (int i = 0; i < 8; ++i)
        #pragma unroll
        for (int j = 0; j < 4; ++j) acc2[i][j] = 0ull;

    TileCtx tc;
    gemm_core(Aseg, Wseg, 3, 3072, acc2, tc);

    float* out = g_gates + (size_t)gate * BH;
    #pragma unroll
    for (int i = 0; i < 8; ++i) {
        const long m = tc.bm + tc.m0 + i;
        float* orow = out + m * NDIM;
        #pragma unroll
        for (int half = 0; half < 2; ++half) {
            const long col = tc.bn + (half == 0 ? tc.nA : tc.nB);
            float2 v0 = unpack2(acc2[i][half * 2 + 0]);
            float2 v1 = unpack2(acc2[i][half * 2 + 1]);
            float4 r;
            r.x = v0.x + bsel[col + 0];
            r.y = v0.y + bsel[col + 1];
            r.z = v1.x + bsel[col + 2];
            r.w = v1.y + bsel[col + 3];
            if (gate < 3) {
                r.x = sigmoidf_fast(r.x); r.y = sigmoidf_fast(r.y);
                r.z = sigmoidf_fast(r.z); r.w = sigmoidf_fast(r.w);
            } else {
                r.x = tanhf(r.x); r.y = tanhf(r.y);
                r.z = tanhf(r.z); r.w = tanhf(r.w);
            }
            *(float4*)(orow + col) = r;
        }
    }
}

// ---------------------------------------------------------------------------
// Kernel 2: cell = f*c_prev + i*g ; hidden = o*tanh(cell)
//   writes hidden -> out[BH .. 2BH), cell -> out[2BH .. 3BH)
// ---------------------------------------------------------------------------
__global__ void cellhid_kernel(const float* __restrict__ cprev,
                               float* __restrict__ out)
{
    const size_t i = ((size_t)blockIdx.x * blockDim.x + threadIdx.x) * 4;
    float4 gi = *(const float4*)&g_gates[i];
    float4 gf = *(const float4*)&g_gates[BH + i];
    float4 go = *(const float4*)&g_gates[2 * BH + i];
    float4 gg = *(const float4*)&g_gates[3 * BH + i];
    float4 cp = *(const float4*)&cprev[i];
    float4 c, h;
    c.x = gf.x * cp.x + gi.x * gg.x;  h.x = go.x * tanhf(c.x);
    c.y = gf.y * cp.y + gi.y * gg.y;  h.y = go.y * tanhf(c.y);
    c.z = gf.z * cp.z + gi.z * gg.z;  h.z = go.z * tanhf(c.z);
    c.w = gf.w * cp.w + gi.w * gg.w;  h.w = go.w * tanhf(c.w);
    *(float4*)&out[BH + i]     = h;
    *(float4*)&out[2 * BH + i] = c;
}

// ---------------------------------------------------------------------------
// Kernel 3/4: generic GEMM  out = [addend +] A@W^T + bias0 [+ bias1]
//   up to 2 K-segments (each 1024), W row stride = wstride
// ---------------------------------------------------------------------------
__global__ void __launch_bounds__(256, 2)
gemm_kernel(const float* __restrict__ A0, const float* __restrict__ A1,
            const float* __restrict__ W0, const float* __restrict__ W1,
            int nseg, int wstride,
            const float* __restrict__ bias0, const float* __restrict__ bias1,
            const float* __restrict__ addend,
            float* __restrict__ out)
{
    const float* Aseg[3] = {A0, A1, nullptr};
    const float* Wseg[3] = {W0, W1, nullptr};

    unsigned long long acc2[8][4];
    #pragma unroll
    for (int i = 0; i < 8; ++i)
        #pragma unroll
        for (int j = 0; j < 4; ++j) acc2[i][j] = 0ull;

    TileCtx tc;
    gemm_core(Aseg, Wseg, nseg, wstride, acc2, tc);

    #pragma unroll
    for (int i = 0; i < 8; ++i) {
        const long m = tc.bm + tc.m0 + i;
        float* orow = out + m * NDIM;
        const float* arow = addend ? addend + m * NDIM : nullptr;
        #pragma unroll
        for (int half = 0; half < 2; ++half) {
            const long col = tc.bn + (half == 0 ? tc.nA : tc.nB);
            float2 v0 = unpack2(acc2[i][half * 2 + 0]);
            float2 v1 = unpack2(acc2[i][half * 2 + 1]);
            float4 r = make_float4(v0.x, v0.y, v1.x, v1.y);
            r.x += bias0[col + 0]; r.y += bias0[col + 1];
            r.z += bias0[col + 2]; r.w += bias0[col + 3];
            if (bias1) {
                r.x += bias1[col + 0]; r.y += bias1[col + 1];
                r.z += bias1[col + 2]; r.w += bias1[col + 3];
            }
            if (arow) {
                float4 a = *(const float4*)(arow + col);
                r.x += a.x; r.y += a.y; r.z += a.z; r.w += a.w;
            }
            *(float4*)(orow + col) = r;
        }
    }
}

// ---------------------------------------------------------------------------
// kernel_launch
// ---------------------------------------------------------------------------
extern "C" void kernel_launch(void* const* d_in, const int* in_sizes, int n_in,
                              void* d_out, int out_size)
{
    const float* emb   = (const float*)d_in[0];
    const float* hid   = (const float*)d_in[1];
    const float* cprev = (const float*)d_in[2];
    const float* ctx   = (const float*)d_in[3];
    const float* Wi = (const float*)d_in[4];  const float* bi = (const float*)d_in[5];
    const float* Wf = (const float*)d_in[6];  const float* bf = (const float*)d_in[7];
    const float* Wo = (const float*)d_in[8];  const float* bo = (const float*)d_in[9];
    const float* Wg = (const float*)d_in[10]; const float* bg = (const float*)d_in[11];
    const float* Wc = (const float*)d_in[12]; const float* bc = (const float*)d_in[13];
    const float* Wh = (const float*)d_in[14]; const float* bh = (const float*)d_in[15];
    const float* Wp = (const float*)d_in[16]; const float* bp = (const float*)d_in[17];
    float* out = (float*)d_out;

    static float* resid_ptr = nullptr;
    if (!resid_ptr) {
        cudaGetSymbolAddress((void**)&resid_ptr, g_resid);
    }

    // 1) four gate GEMMs (K=3072), fused epilogue activations -> g_gates
    gates_kernel<<<dim3(MDIM / BM, NDIM / BN, 4), 256>>>(
        emb, hid, ctx, Wi, Wf, Wo, Wg, bi, bf, bo, bg);

    // 2) cell & hidden elementwise -> out[BH..2BH) hidden, out[2BH..3BH) cell
    cellhid_kernel<<<(int)(BH / 4 / 256), 256>>>(cprev, out);

    // 3) resid = emb + hidden@Wh^T + bh + ctx@Wc^T + bc   (K = 2048)
    gemm_kernel<<<dim3(MDIM / BM, NDIM / BN), 256>>>(
        out + BH /*hidden*/, ctx, Wh, Wc, 2, 1024, bh, bc, emb, resid_ptr);

    // 4) prediction = resid@Wp^T + bp -> out[0..BH)
    gemm_kernel<<<dim3(MDIM / BM, NDIM / BN), 256>>>(
        resid_ptr, nullptr, Wp, nullptr, 1, 1024, bp, nullptr, nullptr, out);
}

// round 4
// speedup vs baseline: 2.9099x; 2.8953x over previous
#include <cuda_runtime.h>
#include <cuda_bf16.h>
#include <cstdint>

// ===========================================================================
// LSTM attention cell via mma.sync bf16 (hi/lo split, 3 fused combos, f32 acc)
// B=4096, E=H=C=1024, D=3072.  out = [pred | hidden | cell]
// Packed operand layout: per 32-k chunk, each row holds [32 hi bf16 | 32 lo bf16]
// = 128 bytes, XOR-swizzled in smem for conflict-free ldmatrix.
// ===========================================================================

#define BHsz (4096ull * 1024ull)

__device__ __nv_bfloat16 g_Apk [4096ull * 6144];   // [emb|hid|ctx] K=3072 packed
__device__ __nv_bfloat16 g_Wpk [4096ull * 6144];   // rows Wi,Wf,Wo,Wg packed
__device__ __nv_bfloat16 g_Ahcpk[4096ull * 4096];  // [hidden|ctx]  K=2048 packed
__device__ __nv_bfloat16 g_Bhcpk[1024ull * 4096];  // rows [Wh|Wc]  packed
__device__ __nv_bfloat16 g_Wppk [1024ull * 2048];  // Wp K=1024 packed
__device__ __nv_bfloat16 g_respk[4096ull * 2048];  // resid K=1024 packed
__device__ float g_gates[4ull * 4096ull * 1024];   // activated i,f,o,g
__device__ float g_biascat[4096];                  // [bi|bf|bo|bg]

// ------------------------------ helpers ------------------------------------
__device__ __forceinline__ uint32_t smem_u32(const void* p) {
    uint32_t a;
    asm("{ .reg .u64 t; cvta.to.shared.u64 t, %1; cvt.u32.u64 %0, t; }"
        : "=r"(a) : "l"(p));
    return a;
}
__device__ __forceinline__ void cp_async16(uint32_t s, const void* g) {
    asm volatile("cp.async.cg.shared.global [%0], [%1], 16;\n"
                 :: "r"(s), "l"(g) : "memory");
}
__device__ __forceinline__ void cp_commit() {
    asm volatile("cp.async.commit_group;\n" ::: "memory");
}
template <int N>
__device__ __forceinline__ void cp_wait() {
    asm volatile("cp.async.wait_group %0;\n" :: "n"(N) : "memory");
}
__device__ __forceinline__ void ldsm4(uint32_t (&r)[4], uint32_t addr) {
    asm volatile("ldmatrix.sync.aligned.m8n8.x4.shared.b16 {%0,%1,%2,%3}, [%4];"
                 : "=r"(r[0]), "=r"(r[1]), "=r"(r[2]), "=r"(r[3]) : "r"(addr));
}
__device__ __forceinline__ void mma16816(float (&c)[4], const uint32_t (&a)[4],
                                         uint32_t b0, uint32_t b1) {
    asm volatile(
        "mma.sync.aligned.m16n8k16.row.col.f32.bf16.bf16.f32 "
        "{%0,%1,%2,%3}, {%4,%5,%6,%7}, {%8,%9}, {%0,%1,%2,%3};"
        : "+f"(c[0]), "+f"(c[1]), "+f"(c[2]), "+f"(c[3])
        : "r"(a[0]), "r"(a[1]), "r"(a[2]), "r"(a[3]), "r"(b0), "r"(b1));
}
__device__ __forceinline__ float sigm(float x) { return 1.0f / (1.0f + __expf(-x)); }
__device__ __forceinline__ void split1(float x, __nv_bfloat16& h, __nv_bfloat16& l) {
    h = __float2bfloat16(x);
    l = __float2bfloat16(x - __bfloat162float(h));
}
// packed element offset for (k) within a row: chunk (k>>5), hi at +0, lo at +32
__device__ __forceinline__ size_t pko(size_t k) { return (k >> 5) * 64 + (k & 31); }

// ===========================================================================
// GEMM: C[4096 or B, N] = A @ B^T with hi/lo packed operands, 3 fused combos.
// Block 128x128, 8 warps (2x4), warp tile m64 x n32, k-chunk 32, 3-stage pipe.
// MODE 0: gates   -> g_gates, bias=g_biascat(arg bias0), sigmoid/tanh by n>>10
// MODE 1: resid   -> g_respk (packed), v += bias0+bias1+addend
// MODE 2: pred    -> outf, v += bias0
// ===========================================================================
template <int MODE>
__global__ void __launch_bounds__(256, 2)
gemm_ms(const __nv_bfloat16* __restrict__ Apk, const __nv_bfloat16* __restrict__ Bpk,
        int arow_len, int brow_len, int nchunks,
        const float* __restrict__ bias0, const float* __restrict__ bias1,
        const float* __restrict__ addend, float* __restrict__ outf,
        __nv_bfloat16* __restrict__ outpk)
{
    extern __shared__ char smem_raw[];
    const uint32_t sbase = smem_u32(smem_raw);
    constexpr uint32_t STAGE = 256 * 128;   // 32 KB: A rows 0-127, B rows 128-255

    const int tid = threadIdx.x, wid = tid >> 5, lane = tid & 31;
    const int wm = wid & 1, wn = wid >> 1;          // 2 x 4 warps
    const long bm = (long)blockIdx.x * 128;
    const long bn = (long)blockIdx.y * 128;

    float acc[4][4][4];
    #pragma unroll
    for (int f = 0; f < 4; ++f)
        #pragma unroll
        for (int n = 0; n < 4; ++n)
            #pragma unroll
            for (int e = 0; e < 4; ++e) acc[f][n][e] = 0.0f;

    const int r0 = tid >> 3, u0 = tid & 7;

    auto load_chunk = [&](int c, int stg) {
        const uint32_t sb = sbase + (uint32_t)stg * STAGE;
        #pragma unroll
        for (int j = 0; j < 4; ++j) {           // A rows
            const int row = r0 + j * 32;
            const __nv_bfloat16* src = Apk + (size_t)(bm + row) * arow_len
                                           + (size_t)c * 64 + u0 * 8;
            cp_async16(sb + row * 128 + ((u0 ^ (row & 7)) << 4), src);
        }
        #pragma unroll
        for (int j = 0; j < 4; ++j) {           // B rows
            const int row = r0 + j * 32;        // 0..127 local
            const __nv_bfloat16* src = Bpk + (size_t)(bn + row) * brow_len
                                           + (size_t)c * 64 + u0 * 8;
            const int srow = row + 128;
            cp_async16(sb + srow * 128 + ((u0 ^ (srow & 7)) << 4), src);
        }
        cp_commit();
    };

    load_chunk(0, 0);
    load_chunk(1, 1);

    const int g = lane >> 3, l7 = lane & 7;

    for (int c = 0; c < nchunks; ++c) {
        cp_wait<1>();
        __syncthreads();

        const uint32_t sb = sbase + (uint32_t)(c % 3) * STAGE;
        #pragma unroll
        for (int s = 0; s < 2; ++s) {           // two k16 steps
            uint32_t Ahi[4][4], Alo[4][4];
            #pragma unroll
            for (int f = 0; f < 4; ++f) {
                const int row = wm * 64 + f * 16 + ((g & 1) << 3) + l7;
                const int ch = 2 * s + (g >> 1);        // hi cols 0-3
                const int cl = 4 + 2 * s + (g >> 1);    // lo cols 4-7
                ldsm4(Ahi[f], sb + row * 128 + ((ch ^ (row & 7)) << 4));
                ldsm4(Alo[f], sb + row * 128 + ((cl ^ (row & 7)) << 4));
            }
            #pragma unroll
            for (int p = 0; p < 2; ++p) {       // two n16 groups
                const int row = 128 + wn * 32 + p * 16 + ((g >> 1) << 3) + l7;
                const int ch = 2 * s + (g & 1);
                const int cl = 4 + 2 * s + (g & 1);
                uint32_t Bhi[4], Blo[4];
                ldsm4(Bhi, sb + row * 128 + ((ch ^ (row & 7)) << 4));
                ldsm4(Blo, sb + row * 128 + ((cl ^ (row & 7)) << 4));
                #pragma unroll
                for (int f = 0; f < 4; ++f) {
                    mma16816(acc[f][2 * p],     Ahi[f], Bhi[0], Bhi[1]);
                    mma16816(acc[f][2 * p + 1], Ahi[f], Bhi[2], Bhi[3]);
                    mma16816(acc[f][2 * p],     Ahi[f], Blo[0], Blo[1]);
                    mma16816(acc[f][2 * p + 1], Ahi[f], Blo[2], Blo[3]);
                    mma16816(acc[f][2 * p],     Alo[f], Bhi[0], Bhi[1]);
                    mma16816(acc[f][2 * p + 1], Alo[f], Bhi[2], Bhi[3]);
                }
            }
        }
        __syncthreads();
        if (c + 2 < nchunks) load_chunk(c + 2, (c + 2) % 3);
        else cp_commit();
    }

    // ------------------------------ epilogue -------------------------------
    const int tg = lane >> 2, tl = lane & 3;
    #pragma unroll
    for (int f = 0; f < 4; ++f) {
        #pragma unroll
        for (int nf = 0; nf < 4; ++nf) {
            const long n = bn + wn * 32 + nf * 8 + tl * 2;
            #pragma unroll
            for (int h = 0; h < 2; ++h) {
                const long m = bm + wm * 64 + f * 16 + tg + h * 8;
                float v0 = acc[f][nf][2 * h + 0];
                float v1 = acc[f][nf][2 * h + 1];
                if (MODE == 0) {
                    v0 += bias0[n]; v1 += bias0[n + 1];
                    const int gate = (int)(n >> 10);
                    if (gate < 3) { v0 = sigm(v0); v1 = sigm(v1); }
                    else          { v0 = tanhf(v0); v1 = tanhf(v1); }
                    float* d = g_gates + (size_t)gate * BHsz
                             + (size_t)m * 1024 + (n & 1023);
                    d[0] = v0; d[1] = v1;
                } else if (MODE == 1) {
                    const float* ar = addend + (size_t)m * 1024;
                    v0 += bias0[n] + bias1[n] + ar[n];
                    v1 += bias0[n + 1] + bias1[n + 1] + ar[n + 1];
                    __nv_bfloat16 hh, ll;
                    __nv_bfloat16* d = outpk + (size_t)m * 2048;
                    split1(v0, hh, ll); d[pko(n)] = hh;     d[pko(n) + 32] = ll;
                    split1(v1, hh, ll); d[pko(n + 1)] = hh; d[pko(n + 1) + 32] = ll;
                } else {
                    float* d = outf + (size_t)m * 1024 + n;
                    d[0] = v0 + bias0[n];
                    d[1] = v1 + bias0[n + 1];
                }
            }
        }
    }
}

// ------------------------- conversion kernels ------------------------------
__global__ void convA(const float* __restrict__ emb, const float* __restrict__ hid,
                      const float* __restrict__ ctx)
{
    const size_t i = (size_t)blockIdx.x * 256 + threadIdx.x;  // 4M
    const size_t m = i >> 10, c = i & 1023;
    const size_t po = pko(c);
    __nv_bfloat16 h, l;
    split1(emb[i], h, l);
    g_Apk[m * 6144 + po] = h;        g_Apk[m * 6144 + po + 32] = l;
    split1(hid[i], h, l);
    g_Apk[m * 6144 + 2048 + po] = h; g_Apk[m * 6144 + 2048 + po + 32] = l;
    split1(ctx[i], h, l);
    g_Apk[m * 6144 + 4096 + po] = h; g_Apk[m * 6144 + 4096 + po + 32] = l;
    g_Ahcpk[m * 4096 + 2048 + po] = h; g_Ahcpk[m * 4096 + 2048 + po + 32] = l;
}

__global__ void convW(const float* __restrict__ Wi, const float* __restrict__ Wf,
                      const float* __restrict__ Wo, const float* __restrict__ Wg)
{
    const int r = blockIdx.x;                 // 0..4095
    const int sel = r >> 10;
    const float* W = (sel == 0) ? Wi : (sel == 1) ? Wf : (sel == 2) ? Wo : Wg;
    const float* src = W + (size_t)(r & 1023) * 3072;
    __nv_bfloat16* dst = g_Wpk + (size_t)r * 6144;
    #pragma unroll
    for (int j = 0; j < 12; ++j) {
        const int k = threadIdx.x + j * 256;
        __nv_bfloat16 h, l; split1(src[k], h, l);
        dst[pko(k)] = h; dst[pko(k) + 32] = l;
    }
}

__global__ void convHC(const float* __restrict__ Wh, const float* __restrict__ Wc)
{
    const int r = blockIdx.x;                 // 0..1023
    __nv_bfloat16* dst = g_Bhcpk + (size_t)r * 4096;
    #pragma unroll
    for (int j = 0; j < 8; ++j) {
        const int c = threadIdx.x + j * 256;  // 0..2047
        const float s = (c < 1024) ? Wh[(size_t)r * 1024 + c]
                                   : Wc[(size_t)r * 1024 + (c - 1024)];
        __nv_bfloat16 h, l; split1(s, h, l);
        dst[pko(c)] = h; dst[pko(c) + 32] = l;
    }
}

__global__ void convP(const float* __restrict__ Wp)
{
    const size_t i = (size_t)blockIdx.x * 256 + threadIdx.x;  // 1M
    const size_t r = i >> 10, k = i & 1023;
    __nv_bfloat16 h, l; split1(Wp[i], h, l);
    g_Wppk[r * 2048 + pko(k)] = h;
    g_Wppk[r * 2048 + pko(k) + 32] = l;
}

__global__ void convBias(const float* __restrict__ bi, const float* __restrict__ bf,
                         const float* __restrict__ bo, const float* __restrict__ bg)
{
    const int i = blockIdx.x * 256 + threadIdx.x;             // 4096
    const int sel = i >> 10, c = i & 1023;
    const float* b = (sel == 0) ? bi : (sel == 1) ? bf : (sel == 2) ? bo : bg;
    g_biascat[i] = b[c];
}

// cell = f*c_prev + i*g ; hidden = o*tanh(cell); also split hidden into Ahcpk
__global__ void cellhid_kernel(const float* __restrict__ cprev, float* __restrict__ out)
{
    const size_t i = ((size_t)blockIdx.x * blockDim.x + threadIdx.x) * 4;
    float4 gi = *(const float4*)&g_gates[i];
    float4 gf = *(const float4*)&g_gates[BHsz + i];
    float4 go = *(const float4*)&g_gates[2 * BHsz + i];
    float4 gg = *(const float4*)&g_gates[3 * BHsz + i];
    float4 cp = *(const float4*)&cprev[i];
    float4 c, h;
    c.x = gf.x * cp.x + gi.x * gg.x;  h.x = go.x * tanhf(c.x);
    c.y = gf.y * cp.y + gi.y * gg.y;  h.y = go.y * tanhf(c.y);
    c.z = gf.z * cp.z + gi.z * gg.z;  h.z = go.z * tanhf(c.z);
    c.w = gf.w * cp.w + gi.w * gg.w;  h.w = go.w * tanhf(c.w);
    *(float4*)&out[BHsz + i]     = h;
    *(float4*)&out[2 * BHsz + i] = c;
    const size_t m = i >> 10, c0 = i & 1023;
    const float hv[4] = {h.x, h.y, h.z, h.w};
    __nv_bfloat16* dst = g_Ahcpk + m * 4096;
    #pragma unroll
    for (int j = 0; j < 4; ++j) {
        __nv_bfloat16 hh, ll; split1(hv[j], hh, ll);
        dst[pko(c0 + j)] = hh; dst[pko(c0 + j) + 32] = ll;
    }
}

// ---------------------------------------------------------------------------
extern "C" void kernel_launch(void* const* d_in, const int* in_sizes, int n_in,
                              void* d_out, int out_size)
{
    const float* emb   = (const float*)d_in[0];
    const float* hid   = (const float*)d_in[1];
    const float* cprev = (const float*)d_in[2];
    const float* ctx   = (const float*)d_in[3];
    const float* Wi = (const float*)d_in[4];  const float* bi = (const float*)d_in[5];
    const float* Wf = (const float*)d_in[6];  const float* bf = (const float*)d_in[7];
    const float* Wo = (const float*)d_in[8];  const float* bo = (const float*)d_in[9];
    const float* Wg = (const float*)d_in[10]; const float* bg = (const float*)d_in[11];
    const float* Wc = (const float*)d_in[12]; const float* bc = (const float*)d_in[13];
    const float* Wh = (const float*)d_in[14]; const float* bh = (const float*)d_in[15];
    const float* Wp = (const float*)d_in[16]; const float* bp = (const float*)d_in[17];
    float* out = (float*)d_out;

    static bool init = false;
    static __nv_bfloat16 *Apk, *Wpk, *Ahcpk, *Bhcpk, *Wppk, *respk;
    static float *biascat;
    if (!init) {
        cudaGetSymbolAddress((void**)&Apk, g_Apk);
        cudaGetSymbolAddress((void**)&Wpk, g_Wpk);
        cudaGetSymbolAddress((void**)&Ahcpk, g_Ahcpk);
        cudaGetSymbolAddress((void**)&Bhcpk, g_Bhcpk);
        cudaGetSymbolAddress((void**)&Wppk, g_Wppk);
        cudaGetSymbolAddress((void**)&respk, g_respk);
        cudaGetSymbolAddress((void**)&biascat, g_biascat);
        cudaFuncSetAttribute(gemm_ms<0>, cudaFuncAttributeMaxDynamicSharedMemorySize, 98304);
        cudaFuncSetAttribute(gemm_ms<1>, cudaFuncAttributeMaxDynamicSharedMemorySize, 98304);
        cudaFuncSetAttribute(gemm_ms<2>, cudaFuncAttributeMaxDynamicSharedMemorySize, 98304);
        init = true;
    }

    // 1) fp32 -> packed bf16 hi/lo conversions
    convA<<<16384, 256>>>(emb, hid, ctx);
    convW<<<4096, 256>>>(Wi, Wf, Wo, Wg);
    convHC<<<1024, 256>>>(Wh, Wc);
    convP<<<4096, 256>>>(Wp);
    convBias<<<16, 256>>>(bi, bf, bo, bg);

    // 2) gates GEMM 4096x4096x3072 -> activated g_gates
    gemm_ms<0><<<dim3(32, 32), 256, 98304>>>(
        Apk, Wpk, 6144, 6144, 96, biascat, nullptr, nullptr, nullptr, nullptr);

    // 3) cell/hidden elementwise (+ hidden split into Ahcpk)
    cellhid_kernel<<<(int)(BHsz / 4 / 256), 256>>>(cprev, out);

    // 4) resid = emb + [hidden|ctx]@[Wh|Wc]^T + bh + bc -> g_respk (packed)
    gemm_ms<1><<<dim3(32, 8), 256, 98304>>>(
        Ahcpk, Bhcpk, 4096, 4096, 64, bh, bc, emb, nullptr, respk);

    // 5) pred = resid@Wp^T + bp -> out[0..BH)
    gemm_ms<2><<<dim3(32, 8), 256, 98304>>>(
        respk, Wppk, 2048, 2048, 32, bp, nullptr, nullptr, out, nullptr);
}

// round 5
// speedup vs baseline: 2.9347x; 1.0085x over previous
#include <cuda_runtime.h>
#include <cuda_bf16.h>
#include <cstdint>

// ===========================================================================
// LSTM attention cell via mma.sync bf16 (hi/lo split, 3 fused combos, f32 acc)
// B=4096, E=H=C=1024, D=3072.  out = [pred | hidden | cell]
// Packed operand layout: per 32-k chunk, each row holds [32 hi bf16 | 32 lo bf16]
// = 128 bytes, XOR-swizzled in smem for conflict-free ldmatrix.
// ===========================================================================

#define BHsz (4096ull * 1024ull)

__device__ __nv_bfloat16 g_Apk [4096ull * 6144];   // [emb|hid|ctx] K=3072 packed
__device__ __nv_bfloat16 g_Wpk [4096ull * 6144];   // rows Wi,Wf,Wo,Wg packed
__device__ __nv_bfloat16 g_Ahcpk[4096ull * 4096];  // [hidden|ctx]  K=2048 packed
__device__ __nv_bfloat16 g_Bhcpk[1024ull * 4096];  // rows [Wh|Wc]  packed
__device__ __nv_bfloat16 g_Wppk [1024ull * 2048];  // Wp K=1024 packed
__device__ __nv_bfloat16 g_respk[4096ull * 2048];  // resid K=1024 packed
__device__ float g_gates[4ull * 4096ull * 1024];   // activated i,f,o,g
__device__ float g_biascat[4096];                  // [bi|bf|bo|bg]

// ------------------------------ helpers ------------------------------------
__device__ __forceinline__ uint32_t smem_u32(const void* p) {
    uint32_t a;
    asm("{ .reg .u64 t; cvta.to.shared.u64 t, %1; cvt.u32.u64 %0, t; }"
        : "=r"(a) : "l"(p));
    return a;
}
__device__ __forceinline__ void cp_async16(uint32_t s, const void* g) {
    asm volatile("cp.async.cg.shared.global [%0], [%1], 16;\n"
                 :: "r"(s), "l"(g) : "memory");
}
__device__ __forceinline__ void cp_commit() {
    asm volatile("cp.async.commit_group;\n" ::: "memory");
}
template <int N>
__device__ __forceinline__ void cp_wait() {
    asm volatile("cp.async.wait_group %0;\n" :: "n"(N) : "memory");
}
__device__ __forceinline__ void ldsm4(uint32_t (&r)[4], uint32_t addr) {
    asm volatile("ldmatrix.sync.aligned.m8n8.x4.shared.b16 {%0,%1,%2,%3}, [%4];"
                 : "=r"(r[0]), "=r"(r[1]), "=r"(r[2]), "=r"(r[3]) : "r"(addr));
}
__device__ __forceinline__ void mma16816(float (&c)[4], const uint32_t (&a)[4],
                                         uint32_t b0, uint32_t b1) {
    asm volatile(
        "mma.sync.aligned.m16n8k16.row.col.f32.bf16.bf16.f32 "
        "{%0,%1,%2,%3}, {%4,%5,%6,%7}, {%8,%9}, {%0,%1,%2,%3};"
        : "+f"(c[0]), "+f"(c[1]), "+f"(c[2]), "+f"(c[3])
        : "r"(a[0]), "r"(a[1]), "r"(a[2]), "r"(a[3]), "r"(b0), "r"(b1));
}
__device__ __forceinline__ float sigm(float x) { return 1.0f / (1.0f + __expf(-x)); }
__device__ __forceinline__ float tanh_fast(float x) {
    const float ax = fabsf(x);
    const float e = __expf(-2.0f * ax);
    const float r = (1.0f - e) / (1.0f + e);
    return copysignf(r, x);
}
__device__ __forceinline__ void split1(float x, __nv_bfloat16& h, __nv_bfloat16& l) {
    h = __float2bfloat16(x);
    l = __float2bfloat16(x - __bfloat162float(h));
}
// packed element offset for (k): chunk (k>>5)*64, hi at +0, lo at +32
__device__ __forceinline__ size_t pko(size_t k) { return (k >> 5) * 64 + (k & 31); }

__device__ __forceinline__ uint32_t bf2u(__nv_bfloat16 a, __nv_bfloat16 b) {
    __nv_bfloat162 t = __halves2bfloat162(a, b);
    return reinterpret_cast<uint32_t&>(t);
}
// split 4 consecutive k-values (c % 4 == 0) and store hi uint2 + lo uint2
__device__ __forceinline__ void split_store4(__nv_bfloat16* base, size_t c, float4 v) {
    __nv_bfloat16 h0, h1, h2, h3, l0, l1, l2, l3;
    split1(v.x, h0, l0); split1(v.y, h1, l1);
    split1(v.z, h2, l2); split1(v.w, h3, l3);
    const size_t off = (c >> 5) * 64 + (c & 31);
    uint2 hi; hi.x = bf2u(h0, h1); hi.y = bf2u(h2, h3);
    uint2 lo; lo.x = bf2u(l0, l1); lo.y = bf2u(l2, l3);
    *reinterpret_cast<uint2*>(base + off)      = hi;
    *reinterpret_cast<uint2*>(base + off + 32) = lo;
}

// ===========================================================================
// GEMM: C = A @ B^T with hi/lo packed operands, 3 fused combos.
// Block 128x128, 8 warps (2x4), warp tile m64 x n32, k-chunk 32, 3-stage pipe.
// MODE 0: gates -> g_gates (bias0, sigmoid/tanh by n>>10)
// MODE 1: resid -> g_respk packed (bias0+bias1+addend)
// MODE 2: pred  -> outf (bias0)
// ===========================================================================
template <int MODE>
__global__ void __launch_bounds__(256, 2)
gemm_ms(const __nv_bfloat16* __restrict__ Apk, const __nv_bfloat16* __restrict__ Bpk,
        int arow_len, int brow_len, int nchunks,
        const float* __restrict__ bias0, const float* __restrict__ bias1,
        const float* __restrict__ addend, float* __restrict__ outf,
        __nv_bfloat16* __restrict__ outpk)
{
    extern __shared__ char smem_raw[];
    const uint32_t sbase = smem_u32(smem_raw);
    constexpr uint32_t STAGE = 256 * 128;   // 32 KB: A rows 0-127, B rows 128-255

    const int tid = threadIdx.x, wid = tid >> 5, lane = tid & 31;
    const int wm = wid & 1, wn = wid >> 1;          // 2 x 4 warps
    const long bm = (long)blockIdx.x * 128;
    const long bn = (long)blockIdx.y * 128;

    float acc[4][4][4];
    #pragma unroll
    for (int f = 0; f < 4; ++f)
        #pragma unroll
        for (int n = 0; n < 4; ++n)
            #pragma unroll
            for (int e = 0; e < 4; ++e) acc[f][n][e] = 0.0f;

    const int r0 = tid >> 3, u0 = tid & 7;

    auto load_chunk = [&](int c, int stg) {
        const uint32_t sb = sbase + (uint32_t)stg * STAGE;
        #pragma unroll
        for (int j = 0; j < 4; ++j) {           // A rows
            const int row = r0 + j * 32;
            const __nv_bfloat16* src = Apk + (size_t)(bm + row) * arow_len
                                           + (size_t)c * 64 + u0 * 8;
            cp_async16(sb + row * 128 + ((u0 ^ (row & 7)) << 4), src);
        }
        #pragma unroll
        for (int j = 0; j < 4; ++j) {           // B rows
            const int row = r0 + j * 32;
            const __nv_bfloat16* src = Bpk + (size_t)(bn + row) * brow_len
                                           + (size_t)c * 64 + u0 * 8;
            const int srow = row + 128;
            cp_async16(sb + srow * 128 + ((u0 ^ (srow & 7)) << 4), src);
        }
        cp_commit();
    };

    load_chunk(0, 0);
    load_chunk(1, 1);

    const int g = lane >> 3, l7 = lane & 7;

    for (int c = 0; c < nchunks; ++c) {
        cp_wait<1>();
        __syncthreads();

        const uint32_t sb = sbase + (uint32_t)(c % 3) * STAGE;
        #pragma unroll
        for (int s = 0; s < 2; ++s) {           // two k16 steps
            uint32_t Ahi[4][4], Alo[4][4];
            #pragma unroll
            for (int f = 0; f < 4; ++f) {
                const int row = wm * 64 + f * 16 + ((g & 1) << 3) + l7;
                const int ch = 2 * s + (g >> 1);        // hi cols 0-3
                const int cl = 4 + 2 * s + (g >> 1);    // lo cols 4-7
                ldsm4(Ahi[f], sb + row * 128 + ((ch ^ (row & 7)) << 4));
                ldsm4(Alo[f], sb + row * 128 + ((cl ^ (row & 7)) << 4));
            }
            #pragma unroll
            for (int p = 0; p < 2; ++p) {       // two n16 groups
                const int row = 128 + wn * 32 + p * 16 + ((g >> 1) << 3) + l7;
                const int ch = 2 * s + (g & 1);
                const int cl = 4 + 2 * s + (g & 1);
                uint32_t Bhi[4], Blo[4];
                ldsm4(Bhi, sb + row * 128 + ((ch ^ (row & 7)) << 4));
                ldsm4(Blo, sb + row * 128 + ((cl ^ (row & 7)) << 4));
                #pragma unroll
                for (int f = 0; f < 4; ++f) {
                    mma16816(acc[f][2 * p],     Ahi[f], Bhi[0], Bhi[1]);
                    mma16816(acc[f][2 * p + 1], Ahi[f], Bhi[2], Bhi[3]);
                    mma16816(acc[f][2 * p],     Ahi[f], Blo[0], Blo[1]);
                    mma16816(acc[f][2 * p + 1], Ahi[f], Blo[2], Blo[3]);
                    mma16816(acc[f][2 * p],     Alo[f], Bhi[0], Bhi[1]);
                    mma16816(acc[f][2 * p + 1], Alo[f], Bhi[2], Bhi[3]);
                }
            }
        }
        __syncthreads();
        if (c + 2 < nchunks) load_chunk(c + 2, (c + 2) % 3);
        else cp_commit();
    }

    // ------------------------------ epilogue -------------------------------
    const int tg = lane >> 2, tl = lane & 3;
    #pragma unroll
    for (int f = 0; f < 4; ++f) {
        #pragma unroll
        for (int nf = 0; nf < 4; ++nf) {
            const long n = bn + wn * 32 + nf * 8 + tl * 2;
            #pragma unroll
            for (int h = 0; h < 2; ++h) {
                const long m = bm + wm * 64 + f * 16 + tg + h * 8;
                float v0 = acc[f][nf][2 * h + 0];
                float v1 = acc[f][nf][2 * h + 1];
                if (MODE == 0) {
                    v0 += bias0[n]; v1 += bias0[n + 1];
                    const int gate = (int)(n >> 10);
                    if (gate < 3) { v0 = sigm(v0); v1 = sigm(v1); }
                    else          { v0 = tanh_fast(v0); v1 = tanh_fast(v1); }
                    float* d = g_gates + (size_t)gate * BHsz
                             + (size_t)m * 1024 + (n & 1023);
                    d[0] = v0; d[1] = v1;
                } else if (MODE == 1) {
                    const float* ar = addend + (size_t)m * 1024;
                    v0 += bias0[n] + bias1[n] + ar[n];
                    v1 += bias0[n + 1] + bias1[n + 1] + ar[n + 1];
                    __nv_bfloat16 hh, ll;
                    __nv_bfloat16* d = outpk + (size_t)m * 2048;
                    split1(v0, hh, ll); d[pko(n)] = hh;     d[pko(n) + 32] = ll;
                    split1(v1, hh, ll); d[pko(n + 1)] = hh; d[pko(n + 1) + 32] = ll;
                } else {
                    float* d = outf + (size_t)m * 1024 + n;
                    d[0] = v0 + bias0[n];
                    d[1] = v1 + bias0[n + 1];
                }
            }
        }
    }
}

// --------------------- vectorized conversion kernels -----------------------
// Each thread handles 4 consecutive k (float4 load -> uint2 hi + uint2 lo).
__global__ void convA(const float* __restrict__ emb, const float* __restrict__ hid,
                      const float* __restrict__ ctx)
{
    const size_t i4 = (size_t)blockIdx.x * 256 + threadIdx.x;  // over B*1024/4
    const size_t m = i4 >> 8, c = (i4 & 255) * 4;
    float4 v;
    v = *reinterpret_cast<const float4*>(emb + m * 1024 + c);
    split_store4(g_Apk + m * 6144, c, v);
    v = *reinterpret_cast<const float4*>(hid + m * 1024 + c);
    split_store4(g_Apk + m * 6144 + 2048, c, v);
    v = *reinterpret_cast<const float4*>(ctx + m * 1024 + c);
    split_store4(g_Apk + m * 6144 + 4096, c, v);
    split_store4(g_Ahcpk + m * 4096 + 2048, c, v);
}

__global__ void convW(const float* __restrict__ Wi, const float* __restrict__ Wf,
                      const float* __restrict__ Wo, const float* __restrict__ Wg)
{
    const int r = blockIdx.x;                 // 0..4095
    const int sel = r >> 10;
    const float* W = (sel == 0) ? Wi : (sel == 1) ? Wf : (sel == 2) ? Wo : Wg;
    const float* src = W + (size_t)(r & 1023) * 3072;
    __nv_bfloat16* dst = g_Wpk + (size_t)r * 6144;
    #pragma unroll
    for (int j = 0; j < 3; ++j) {
        const size_t c = (size_t)(threadIdx.x + j * 256) * 4;
        split_store4(dst, c, *reinterpret_cast<const float4*>(src + c));
    }
}

__global__ void convHC(const float* __restrict__ Wh, const float* __restrict__ Wc)
{
    const int r = blockIdx.x;                 // 0..1023
    __nv_bfloat16* dst = g_Bhcpk + (size_t)r * 4096;
    #pragma unroll
    for (int j = 0; j < 2; ++j) {
        const size_t c = (size_t)(threadIdx.x + j * 256) * 4;
        const float* src = (c < 1024) ? (Wh + (size_t)r * 1024 + c)
                                      : (Wc + (size_t)r * 1024 + (c - 1024));
        split_store4(dst, c, *reinterpret_cast<const float4*>(src));
    }
}

__global__ void convP(const float* __restrict__ Wp)
{
    const int r = blockIdx.x;                 // 0..1023
    const size_t c = (size_t)threadIdx.x * 4;
    split_store4(g_Wppk + (size_t)r * 2048, c,
                 *reinterpret_cast<const float4*>(Wp + (size_t)r * 1024 + c));
}

__global__ void convBias(const float* __restrict__ bi, const float* __restrict__ bf,
                         const float* __restrict__ bo, const float* __restrict__ bg)
{
    const int i = blockIdx.x * 256 + threadIdx.x;             // 4096
    const int sel = i >> 10, c = i & 1023;
    const float* b = (sel == 0) ? bi : (sel == 1) ? bf : (sel == 2) ? bo : bg;
    g_biascat[i] = b[c];
}

// cell = f*c_prev + i*g ; hidden = o*tanh(cell); split hidden into Ahcpk
__global__ void cellhid_kernel(const float* __restrict__ cprev, float* __restrict__ out)
{
    const size_t i = ((size_t)blockIdx.x * blockDim.x + threadIdx.x) * 4;
    float4 gi = *(const float4*)&g_gates[i];
    float4 gf = *(const float4*)&g_gates[BHsz + i];
    float4 go = *(const float4*)&g_gates[2 * BHsz + i];
    float4 gg = *(const float4*)&g_gates[3 * BHsz + i];
    float4 cp = *(const float4*)&cprev[i];
    float4 c, h;
    c.x = gf.x * cp.x + gi.x * gg.x;  h.x = go.x * tanh_fast(c.x);
    c.y = gf.y * cp.y + gi.y * gg.y;  h.y = go.y * tanh_fast(c.y);
    c.z = gf.z * cp.z + gi.z * gg.z;  h.z = go.z * tanh_fast(c.z);
    c.w = gf.w * cp.w + gi.w * gg.w;  h.w = go.w * tanh_fast(c.w);
    *(float4*)&out[BHsz + i]     = h;
    *(float4*)&out[2 * BHsz + i] = c;
    const size_t m = i >> 10, c0 = i & 1023;
    split_store4(g_Ahcpk + m * 4096, c0, h);
}

// ---------------------------------------------------------------------------
extern "C" void kernel_launch(void* const* d_in, const int* in_sizes, int n_in,
                              void* d_out, int out_size)
{
    const float* emb   = (const float*)d_in[0];
    const float* hid   = (const float*)d_in[1];
    const float* cprev = (const float*)d_in[2];
    const float* ctx   = (const float*)d_in[3];
    const float* Wi = (const float*)d_in[4];  const float* bi = (const float*)d_in[5];
    const float* Wf = (const float*)d_in[6];  const float* bf = (const float*)d_in[7];
    const float* Wo = (const float*)d_in[8];  const float* bo = (const float*)d_in[9];
    const float* Wg = (const float*)d_in[10]; const float* bg = (const float*)d_in[11];
    const float* Wc = (const float*)d_in[12]; const float* bc = (const float*)d_in[13];
    const float* Wh = (const float*)d_in[14]; const float* bh = (const float*)d_in[15];
    const float* Wp = (const float*)d_in[16]; const float* bp = (const float*)d_in[17];
    float* out = (float*)d_out;

    static bool init = false;
    static __nv_bfloat16 *Apk, *Wpk, *Ahcpk, *Bhcpk, *Wppk, *respk;
    static float *biascat;
    if (!init) {
        cudaGetSymbolAddress((void**)&Apk, g_Apk);
        cudaGetSymbolAddress((void**)&Wpk, g_Wpk);
        cudaGetSymbolAddress((void**)&Ahcpk, g_Ahcpk);
        cudaGetSymbolAddress((void**)&Bhcpk, g_Bhcpk);
        cudaGetSymbolAddress((void**)&Wppk, g_Wppk);
        cudaGetSymbolAddress((void**)&respk, g_respk);
        cudaGetSymbolAddress((void**)&biascat, g_biascat);
        cudaFuncSetAttribute(gemm_ms<0>, cudaFuncAttributeMaxDynamicSharedMemorySize, 98304);
        cudaFuncSetAttribute(gemm_ms<1>, cudaFuncAttributeMaxDynamicSharedMemorySize, 98304);
        cudaFuncSetAttribute(gemm_ms<2>, cudaFuncAttributeMaxDynamicSharedMemorySize, 98304);
        init = true;
    }

    // 1) fp32 -> packed bf16 hi/lo conversions (vectorized)
    convA<<<4096, 256>>>(emb, hid, ctx);
    convW<<<4096, 256>>>(Wi, Wf, Wo, Wg);
    convHC<<<1024, 256>>>(Wh, Wc);
    convP<<<1024, 256>>>(Wp);
    convBias<<<16, 256>>>(bi, bf, bo, bg);

    // 2) gates GEMM 4096x4096x3072 -> activated g_gates
    gemm_ms<0><<<dim3(32, 32), 256, 98304>>>(
        Apk, Wpk, 6144, 6144, 96, biascat, nullptr, nullptr, nullptr, nullptr);

    // 3) cell/hidden elementwise (+ hidden split into Ahcpk)
    cellhid_kernel<<<(int)(BHsz / 4 / 256), 256>>>(cprev, out);

    // 4) resid = emb + [hidden|ctx]@[Wh|Wc]^T + bh + bc -> g_respk (packed)
    gemm_ms<1><<<dim3(32, 8), 256, 98304>>>(
        Ahcpk, Bhcpk, 4096, 4096, 64, bh, bc, emb, nullptr, respk);

    // 5) pred = resid@Wp^T + bp -> out[0..BH)
    gemm_ms<2><<<dim3(32, 8), 256, 98304>>>(
        respk, Wppk, 2048, 2048, 32, bp, nullptr, nullptr, out, nullptr);
}

// round 7
// speedup vs baseline: 3.9439x; 1.3439x over previous
#include <cuda_runtime.h>
#include <cuda_fp16.h>
#include <cstdint>

// ===========================================================================
// LSTM attention cell via mma.sync fp16 (hi/lo split, 2-pass: A*hi(B) exact in
// A), f32 accumulate. B=4096, E=H=C=1024, D=3072. out = [pred | hidden | cell]
// Packed operand rows: per 32-k chunk [32 hi fp16 | 32 lo fp16] = 128 bytes.
// Only A's lo is consumed by MMA (C = Ahi*Bhi + Alo*Bhi = A*Bhi).
// ===========================================================================

#define BHsz (4096ull * 1024ull)

__device__ __half g_Apk [4096ull * 6144];   // [emb|hid|ctx] K=3072 packed
__device__ __half g_Wpk [4096ull * 6144];   // rows Wi,Wf,Wo,Wg stacked
__device__ __half g_Ahcpk[4096ull * 4096];  // [hidden|ctx]  K=2048 packed
__device__ __half g_Bhcpk[1024ull * 4096];  // rows [Wh|Wc]  packed
__device__ __half g_Wppk [1024ull * 2048];  // Wp K=1024 packed
__device__ __half g_respk[4096ull * 2048];  // resid K=1024 packed
__device__ float g_gates[4ull * 4096ull * 1024];   // activated i,f,o,g
__device__ float g_biascat[4096];                  // [bi|bf|bo|bg]

// ------------------------------ helpers ------------------------------------
__device__ __forceinline__ uint32_t smem_u32(const void* p) {
    uint32_t a;
    asm("{ .reg .u64 t; cvta.to.shared.u64 t, %1; cvt.u32.u64 %0, t; }"
        : "=r"(a) : "l"(p));
    return a;
}
__device__ __forceinline__ void cp_async16(uint32_t s, const void* g) {
    asm volatile("cp.async.cg.shared.global [%0], [%1], 16;\n"
                 :: "r"(s), "l"(g) : "memory");
}
__device__ __forceinline__ void cp_commit() {
    asm volatile("cp.async.commit_group;\n" ::: "memory");
}
template <int N>
__device__ __forceinline__ void cp_wait() {
    asm volatile("cp.async.wait_group %0;\n" :: "n"(N) : "memory");
}
__device__ __forceinline__ void ldsm4(uint32_t (&r)[4], uint32_t addr) {
    asm volatile("ldmatrix.sync.aligned.m8n8.x4.shared.b16 {%0,%1,%2,%3}, [%4];"
                 : "=r"(r[0]), "=r"(r[1]), "=r"(r[2]), "=r"(r[3]) : "r"(addr));
}
__device__ __forceinline__ void mma16816(float (&c)[4], const uint32_t (&a)[4],
                                         uint32_t b0, uint32_t b1) {
    asm volatile(
        "mma.sync.aligned.m16n8k16.row.col.f32.f16.f16.f32 "
        "{%0,%1,%2,%3}, {%4,%5,%6,%7}, {%8,%9}, {%0,%1,%2,%3};"
        : "+f"(c[0]), "+f"(c[1]), "+f"(c[2]), "+f"(c[3])
        : "r"(a[0]), "r"(a[1]), "r"(a[2]), "r"(a[3]), "r"(b0), "r"(b1));
}
__device__ __forceinline__ float sigm(float x) { return 1.0f / (1.0f + __expf(-x)); }
__device__ __forceinline__ float tanh_fast(float x) {
    const float ax = fabsf(x);
    const float e = __expf(-2.0f * ax);
    const float r = (1.0f - e) / (1.0f + e);
    return copysignf(r, x);
}
__device__ __forceinline__ void split1(float x, __half& h, __half& l) {
    h = __float2half_rn(x);
    l = __float2half_rn(x - __half2float(h));
}
// packed element offset for (k): chunk (k>>5)*64, hi at +0, lo at +32
__device__ __forceinline__ size_t pko(size_t k) { return (k >> 5) * 64 + (k & 31); }

__device__ __forceinline__ uint32_t h2u(__half a, __half b) {
    __half2 t = __halves2half2(a, b);
    return reinterpret_cast<uint32_t&>(t);
}
// split 4 consecutive k-values (c % 4 == 0): hi uint2 + lo uint2 stores
__device__ __forceinline__ void split_store4(__half* base, size_t c, float4 v) {
    __half h0, h1, h2, h3, l0, l1, l2, l3;
    split1(v.x, h0, l0); split1(v.y, h1, l1);
    split1(v.z, h2, l2); split1(v.w, h3, l3);
    const size_t off = (c >> 5) * 64 + (c & 31);
    uint2 hi; hi.x = h2u(h0, h1); hi.y = h2u(h2, h3);
    uint2 lo; lo.x = h2u(l0, l1); lo.y = h2u(l2, l3);
    *reinterpret_cast<uint2*>(base + off)      = hi;
    *reinterpret_cast<uint2*>(base + off + 32) = lo;
}

// ===========================================================================
// GEMM: C = A @ B^T, 2 fused combos (AhiBhi + AloBhi = A*Bhi), persistent tiles.
// Block 128x128, 8 warps (2x4), warp tile m64 x n32, k-chunk 32, 3-stage pipe.
// M tiles fixed at 32 (M=4096): tile t -> bm=(t&31)*128, bn=(t>>5)*128.
// MODE 0: gates -> g_gates (bias0, sigmoid/tanh by n>>10)
// MODE 1: resid -> g_respk packed (bias0+bias1+addend)
// MODE 2: pred  -> outf (bias0)
// ===========================================================================
template <int MODE>
__global__ void __launch_bounds__(256, 2)
gemm_ms(const __half* __restrict__ Apk, const __half* __restrict__ Bpk,
        int arow_len, int brow_len, int nchunks, int ntile_total,
        const float* __restrict__ bias0, const float* __restrict__ bias1,
        const float* __restrict__ addend, float* __restrict__ outf,
        __half* __restrict__ outpk)
{
    extern __shared__ char smem_raw[];
    const uint32_t sbase = smem_u32(smem_raw);
    constexpr uint32_t STAGE = 256 * 128;   // 32 KB: A rows 0-127, B rows 128-255

    const int tid = threadIdx.x, wid = tid >> 5, lane = tid & 31;
    const int wm = wid & 1, wn = wid >> 1;          // 2 x 4 warps
    const int r0 = tid >> 3, u0 = tid & 7;
    const int g = lane >> 3, l7 = lane & 7;
    const int tg = lane >> 2, tl = lane & 3;

    for (int t = blockIdx.x; t < ntile_total; t += gridDim.x) {
        const long bm = (long)(t & 31) * 128;
        const long bn = (long)(t >> 5) * 128;

        float acc[4][4][4];
        #pragma unroll
        for (int f = 0; f < 4; ++f)
            #pragma unroll
            for (int n = 0; n < 4; ++n)
                #pragma unroll
                for (int e = 0; e < 4; ++e) acc[f][n][e] = 0.0f;

        auto load_chunk = [&](int c, int stg) {
            const uint32_t sb = sbase + (uint32_t)stg * STAGE;
            #pragma unroll
            for (int j = 0; j < 4; ++j) {           // A rows
                const int row = r0 + j * 32;
                const __half* src = Apk + (size_t)(bm + row) * arow_len
                                        + (size_t)c * 64 + u0 * 8;
                cp_async16(sb + row * 128 + ((u0 ^ (row & 7)) << 4), src);
            }
            #pragma unroll
            for (int j = 0; j < 4; ++j) {           // B rows
                const int row = r0 + j * 32;
                const __half* src = Bpk + (size_t)(bn + row) * brow_len
                                        + (size_t)c * 64 + u0 * 8;
                const int srow = row + 128;
                cp_async16(sb + srow * 128 + ((u0 ^ (srow & 7)) << 4), src);
            }
            cp_commit();
        };

        load_chunk(0, 0);
        load_chunk(1, 1);

        for (int c = 0; c < nchunks; ++c) {
            cp_wait<1>();
            __syncthreads();                       // single sync per chunk

            if (c + 2 < nchunks) load_chunk(c + 2, (c + 2) % 3);
            else cp_commit();

            const uint32_t sb = sbase + (uint32_t)(c % 3) * STAGE;
            #pragma unroll
            for (int s = 0; s < 2; ++s) {          // two k16 steps
                uint32_t Ahi[4][4], Alo[4][4];
                #pragma unroll
                for (int f = 0; f < 4; ++f) {
                    const int row = wm * 64 + f * 16 + ((g & 1) << 3) + l7;
                    const int ch = 2 * s + (g >> 1);        // hi cols 0-3
                    const int cl = 4 + 2 * s + (g >> 1);    // lo cols 4-7
                    ldsm4(Ahi[f], sb + row * 128 + ((ch ^ (row & 7)) << 4));
                    ldsm4(Alo[f], sb + row * 128 + ((cl ^ (row & 7)) << 4));
                }
                #pragma unroll
                for (int p = 0; p < 2; ++p) {      // two n16 groups (hi only)
                    const int row = 128 + wn * 32 + p * 16 + ((g >> 1) << 3) + l7;
                    const int ch = 2 * s + (g & 1);
                    uint32_t Bhi[4];
                    ldsm4(Bhi, sb + row * 128 + ((ch ^ (row & 7)) << 4));
                    #pragma unroll
                    for (int f = 0; f < 4; ++f) {
                        mma16816(acc[f][2 * p],     Ahi[f], Bhi[0], Bhi[1]);
                        mma16816(acc[f][2 * p + 1], Ahi[f], Bhi[2], Bhi[3]);
                        mma16816(acc[f][2 * p],     Alo[f], Bhi[0], Bhi[1]);
                        mma16816(acc[f][2 * p + 1], Alo[f], Bhi[2], Bhi[3]);
                    }
                }
            }
        }

        // ---------------------------- epilogue -----------------------------
        #pragma unroll
        for (int f = 0; f < 4; ++f) {
            #pragma unroll
            for (int nf = 0; nf < 4; ++nf) {
                const long n = bn + wn * 32 + nf * 8 + tl * 2;
                #pragma unroll
                for (int h = 0; h < 2; ++h) {
                    const long m = bm + wm * 64 + f * 16 + tg + h * 8;
                    float v0 = acc[f][nf][2 * h + 0];
                    float v1 = acc[f][nf][2 * h + 1];
                    if (MODE == 0) {
                        v0 += bias0[n]; v1 += bias0[n + 1];
                        const int gate = (int)(n >> 10);
                        if (gate < 3) { v0 = sigm(v0); v1 = sigm(v1); }
                        else          { v0 = tanh_fast(v0); v1 = tanh_fast(v1); }
                        float* d = g_gates + (size_t)gate * BHsz
                                 + (size_t)m * 1024 + (n & 1023);
                        d[0] = v0; d[1] = v1;
                    } else if (MODE == 1) {
                        const float* ar = addend + (size_t)m * 1024;
                        v0 += bias0[n] + bias1[n] + ar[n];
                        v1 += bias0[n + 1] + bias1[n + 1] + ar[n + 1];
                        __half hh, ll;
                        __half* d = outpk + (size_t)m * 2048;
                        split1(v0, hh, ll); d[pko(n)] = hh;     d[pko(n) + 32] = ll;
                        split1(v1, hh, ll); d[pko(n + 1)] = hh; d[pko(n + 1) + 32] = ll;
                    } else {
                        float* d = outf + (size_t)m * 1024 + n;
                        d[0] = v0 + bias0[n];
                        d[1] = v1 + bias0[n + 1];
                    }
                }
            }
        }
    }
}

// --------------------- vectorized conversion kernels -----------------------
__global__ void convA(const float* __restrict__ emb, const float* __restrict__ hid,
                      const float* __restrict__ ctx)
{
    const size_t i4 = (size_t)blockIdx.x * 256 + threadIdx.x;  // over B*1024/4
    const size_t m = i4 >> 8, c = (i4 & 255) * 4;
    float4 v;
    v = *reinterpret_cast<const float4*>(emb + m * 1024 + c);
    split_store4(g_Apk + m * 6144, c, v);
    v = *reinterpret_cast<const float4*>(hid + m * 1024 + c);
    split_store4(g_Apk + m * 6144 + 2048, c, v);
    v = *reinterpret_cast<const float4*>(ctx + m * 1024 + c);
    split_store4(g_Apk + m * 6144 + 4096, c, v);
    split_store4(g_Ahcpk + m * 4096 + 2048, c, v);
}

__global__ void convW(const float* __restrict__ Wi, const float* __restrict__ Wf,
                      const float* __restrict__ Wo, const float* __restrict__ Wg)
{
    const int r = blockIdx.x;                 // 0..4095
    const int sel = r >> 10;
    const float* W = (sel == 0) ? Wi : (sel == 1) ? Wf : (sel == 2) ? Wo : Wg;
    const float* src = W + (size_t)(r & 1023) * 3072;
    __half* dst = g_Wpk + (size_t)r * 6144;
    #pragma unroll
    for (int j = 0; j < 3; ++j) {
        const size_t c = (size_t)(threadIdx.x + j * 256) * 4;
        split_store4(dst, c, *reinterpret_cast<const float4*>(src + c));
    }
}

__global__ void convHC(const float* __restrict__ Wh, const float* __restrict__ Wc)
{
    const int r = blockIdx.x;                 // 0..1023
    __half* dst = g_Bhcpk + (size_t)r * 4096;
    #pragma unroll
    for (int j = 0; j < 2; ++j) {
        const size_t c = (size_t)(threadIdx.x + j * 256) * 4;
        const float* src = (c < 1024) ? (Wh + (size_t)r * 1024 + c)
                                      : (Wc + (size_t)r * 1024 + (c - 1024));
        split_store4(dst, c, *reinterpret_cast<const float4*>(src));
    }
}

__global__ void convP(const float* __restrict__ Wp)
{
    const int r = blockIdx.x;                 // 0..1023
    const size_t c = (size_t)threadIdx.x * 4;
    split_store4(g_Wppk + (size_t)r * 2048, c,
                 *reinterpret_cast<const float4*>(Wp + (size_t)r * 1024 + c));
}

__global__ void convBias(const float* __restrict__ bi, const float* __restrict__ bf,
                         const float* __restrict__ bo, const float* __restrict__ bg)
{
    const int i = blockIdx.x * 256 + threadIdx.x;             // 4096
    const int sel = i >> 10, c = i & 1023;
    const float* b = (sel == 0) ? bi : (sel == 1) ? bf : (sel == 2) ? bo : bg;
    g_biascat[i] = b[c];
}

// cell = f*c_prev + i*g ; hidden = o*tanh(cell); split hidden into Ahcpk
__global__ void cellhid_kernel(const float* __restrict__ cprev, float* __restrict__ out)
{
    const size_t i = ((size_t)blockIdx.x * blockDim.x + threadIdx.x) * 4;
    float4 gi = *(const float4*)&g_gates[i];
    float4 gf = *(const float4*)&g_gates[BHsz + i];
    float4 go = *(const float4*)&g_gates[2 * BHsz + i];
    float4 gg = *(const float4*)&g_gates[3 * BHsz + i];
    float4 cp = *(const float4*)&cprev[i];
    float4 c, h;
    c.x = gf.x * cp.x + gi.x * gg.x;  h.x = go.x * tanh_fast(c.x);
    c.y = gf.y * cp.y + gi.y * gg.y;  h.y = go.y * tanh_fast(c.y);
    c.z = gf.z * cp.z + gi.z * gg.z;  h.z = go.z * tanh_fast(c.z);
    c.w = gf.w * cp.w + gi.w * gg.w;  h.w = go.w * tanh_fast(c.w);
    *(float4*)&out[BHsz + i]     = h;
    *(float4*)&out[2 * BHsz + i] = c;
    const size_t m = i >> 10, c0 = i & 1023;
    split_store4(g_Ahcpk + m * 4096, c0, h);
}

// ---------------------------------------------------------------------------
extern "C" void kernel_launch(void* const* d_in, const int* in_sizes, int n_in,
                              void* d_out, int out_size)
{
    const float* emb   = (const float*)d_in[0];
    const float* hid   = (const float*)d_in[1];
    const float* cprev = (const float*)d_in[2];
    const float* ctx   = (const float*)d_in[3];
    const float* Wi = (const float*)d_in[4];  const float* bi = (const float*)d_in[5];
    const float* Wf = (const float*)d_in[6];  const float* bf = (const float*)d_in[7];
    const float* Wo = (const float*)d_in[8];  const float* bo = (const float*)d_in[9];
    const float* Wg = (const float*)d_in[10]; const float* bg = (const float*)d_in[11];
    const float* Wc = (const float*)d_in[12]; const float* bc = (const float*)d_in[13];
    const float* Wh = (const float*)d_in[14]; const float* bh = (const float*)d_in[15];
    const float* Wp = (const float*)d_in[16]; const float* bp = (const float*)d_in[17];
    float* out = (float*)d_out;

    static bool init = false;
    static __half *Apk, *Wpk, *Ahcpk, *Bhcpk, *Wppk, *respk;
    static float *biascat;
    if (!init) {
        cudaGetSymbolAddress((void**)&Apk, g_Apk);
        cudaGetSymbolAddress((void**)&Wpk, g_Wpk);
        cudaGetSymbolAddress((void**)&Ahcpk, g_Ahcpk);
        cudaGetSymbolAddress((void**)&Bhcpk, g_Bhcpk);
        cudaGetSymbolAddress((void**)&Wppk, g_Wppk);
        cudaGetSymbolAddress((void**)&respk, g_respk);
        cudaGetSymbolAddress((void**)&biascat, g_biascat);
        cudaFuncSetAttribute(gemm_ms<0>, cudaFuncAttributeMaxDynamicSharedMemorySize, 98304);
        cudaFuncSetAttribute(gemm_ms<1>, cudaFuncAttributeMaxDynamicSharedMemorySize, 98304);
        cudaFuncSetAttribute(gemm_ms<2>, cudaFuncAttributeMaxDynamicSharedMemorySize, 98304);
        init = true;
    }

    // 1) fp32 -> packed fp16 hi/lo conversions
    convA<<<4096, 256>>>(emb, hid, ctx);
    convW<<<4096, 256>>>(Wi, Wf, Wo, Wg);
    convHC<<<1024, 256>>>(Wh, Wc);
    convP<<<1024, 256>>>(Wp);
    convBias<<<16, 256>>>(bi, bf, bo, bg);

    // 2) gates GEMM 4096x4096x3072 -> activated g_gates (persistent, 1024 tiles)
    gemm_ms<0><<<296, 256, 98304>>>(
        Apk, Wpk, 6144, 6144, 96, 1024, biascat, nullptr, nullptr, nullptr, nullptr);

    // 3) cell/hidden elementwise (+ hidden split into Ahcpk)
    cellhid_kernel<<<(int)(BHsz / 4 / 256), 256>>>(cprev, out);

    // 4) resid = emb + [hidden|ctx]@[Wh|Wc]^T + bh + bc -> g_respk (packed)
    gemm_ms<1><<<256, 256, 98304>>>(
        Ahcpk, Bhcpk, 4096, 4096, 64, 256, bh, bc, emb, nullptr, respk);

    // 5) pred = resid@Wp^T + bp -> out[0..BH)
    gemm_ms<2><<<256, 256, 98304>>>(
        respk, Wppk, 2048, 2048, 32, 256, bp, nullptr, nullptr, out, nullptr);
}

// round 8
// speedup vs baseline: 6.9530x; 1.7630x over previous
#include <cuda_runtime.h>
#include <cuda_fp16.h>
#include <cstdint>

// ===========================================================================
// LSTM attention cell via mma.sync fp16 (single-pass fp16 operands, f32 accum)
// B=4096, E=H=C=1024, D=3072. out = [pred | hidden | cell]
// Plain row-major fp16 operands; 128-byte rows per 64-k chunk in smem (SW128-
// style XOR swizzle), 3-stage cp.async pipeline, persistent CTAs.
// ===========================================================================

#define BHsz (4096ull * 1024ull)

__device__ __half g_Af [4096ull * 3072];   // [emb|hid|ctx] K=3072
__device__ __half g_Wf [4096ull * 3072];   // rows Wi,Wf,Wo,Wg stacked
__device__ __half g_Ahc[4096ull * 2048];   // [hidden|ctx]  K=2048
__device__ __half g_Bhc[1024ull * 2048];   // rows [Wh|Wc]
__device__ __half g_Wpf[1024ull * 1024];   // Wp
__device__ __half g_res[4096ull * 1024];   // resid fp16
__device__ float g_gates[4ull * 4096ull * 1024];   // activated i,f,o,g
__device__ float g_biascat[4096];                  // [bi|bf|bo|bg]

// ------------------------------ helpers ------------------------------------
__device__ __forceinline__ uint32_t smem_u32(const void* p) {
    uint32_t a;
    asm("{ .reg .u64 t; cvta.to.shared.u64 t, %1; cvt.u32.u64 %0, t; }"
        : "=r"(a) : "l"(p));
    return a;
}
__device__ __forceinline__ void cp_async16(uint32_t s, const void* g) {
    asm volatile("cp.async.cg.shared.global [%0], [%1], 16;\n"
                 :: "r"(s), "l"(g) : "memory");
}
__device__ __forceinline__ void cp_commit() {
    asm volatile("cp.async.commit_group;\n" ::: "memory");
}
template <int N>
__device__ __forceinline__ void cp_wait() {
    asm volatile("cp.async.wait_group %0;\n" :: "n"(N) : "memory");
}
__device__ __forceinline__ void ldsm4(uint32_t (&r)[4], uint32_t addr) {
    asm volatile("ldmatrix.sync.aligned.m8n8.x4.shared.b16 {%0,%1,%2,%3}, [%4];"
                 : "=r"(r[0]), "=r"(r[1]), "=r"(r[2]), "=r"(r[3]) : "r"(addr));
}
__device__ __forceinline__ void mma16816(float (&c)[4], const uint32_t (&a)[4],
                                         uint32_t b0, uint32_t b1) {
    asm volatile(
        "mma.sync.aligned.m16n8k16.row.col.f32.f16.f16.f32 "
        "{%0,%1,%2,%3}, {%4,%5,%6,%7}, {%8,%9}, {%0,%1,%2,%3};"
        : "+f"(c[0]), "+f"(c[1]), "+f"(c[2]), "+f"(c[3])
        : "r"(a[0]), "r"(a[1]), "r"(a[2]), "r"(a[3]), "r"(b0), "r"(b1));
}
__device__ __forceinline__ float sigm(float x) { return 1.0f / (1.0f + __expf(-x)); }
__device__ __forceinline__ float tanh_fast(float x) {
    const float ax = fabsf(x);
    const float e = __expf(-2.0f * ax);
    const float r = (1.0f - e) / (1.0f + e);
    return copysignf(r, x);
}
// float4 -> 4 fp16 -> uint2 (8-byte store), elements consecutive
__device__ __forceinline__ void cvt_store4(__half* dst, float4 v) {
    __half2 a = __floats2half2_rn(v.x, v.y);
    __half2 b = __floats2half2_rn(v.z, v.w);
    uint2 u;
    u.x = reinterpret_cast<uint32_t&>(a);
    u.y = reinterpret_cast<uint32_t&>(b);
    *reinterpret_cast<uint2*>(dst) = u;
}

// ===========================================================================
// GEMM: C = A @ B^T, plain fp16 operands, persistent tiles.
// Block 128x128, 8 warps (2x4), warp tile m64 x n32, k-chunk 64, 3-stage pipe.
// M tiles fixed at 32 (M=4096): tile t -> bm=(t&31)*128, bn=(t>>5)*128.
// MODE 0: gates -> g_gates (bias0, sigmoid/tanh by n>>10)
// MODE 1: resid -> g_res fp16 (bias0+bias1+addend)
// MODE 2: pred  -> outf (bias0)
// ===========================================================================
template <int MODE>
__global__ void __launch_bounds__(256, 2)
gemm_ms(const __half* __restrict__ Af, const __half* __restrict__ Bf,
        int arow_len, int brow_len, int nchunks, int ntile_total,
        const float* __restrict__ bias0, const float* __restrict__ bias1,
        const float* __restrict__ addend, float* __restrict__ outf,
        __half* __restrict__ outh)
{
    extern __shared__ char smem_raw[];
    const uint32_t sbase = smem_u32(smem_raw);
    constexpr uint32_t STAGE = 256 * 128;   // 32 KB: A rows 0-127, B rows 128-255

    const int tid = threadIdx.x, wid = tid >> 5, lane = tid & 31;
    const int wm = wid & 1, wn = wid >> 1;          // 2 x 4 warps
    const int r0 = tid >> 3, u0 = tid & 7;
    const int g = lane >> 3, l7 = lane & 7;
    const int tg = lane >> 2, tl = lane & 3;

    for (int t = blockIdx.x; t < ntile_total; t += gridDim.x) {
        const long bm = (long)(t & 31) * 128;
        const long bn = (long)(t >> 5) * 128;

        float acc[4][4][4];
        #pragma unroll
        for (int f = 0; f < 4; ++f)
            #pragma unroll
            for (int n = 0; n < 4; ++n)
                #pragma unroll
                for (int e = 0; e < 4; ++e) acc[f][n][e] = 0.0f;

        auto load_chunk = [&](int c, int stg) {
            const uint32_t sb = sbase + (uint32_t)stg * STAGE;
            #pragma unroll
            for (int j = 0; j < 4; ++j) {           // A rows (64 k = 128 B/row)
                const int row = r0 + j * 32;
                const __half* src = Af + (size_t)(bm + row) * arow_len
                                       + (size_t)c * 64 + u0 * 8;
                cp_async16(sb + row * 128 + ((u0 ^ (row & 7)) << 4), src);
            }
            #pragma unroll
            for (int j = 0; j < 4; ++j) {           // B rows
                const int row = r0 + j * 32;
                const __half* src = Bf + (size_t)(bn + row) * brow_len
                                       + (size_t)c * 64 + u0 * 8;
                const int srow = row + 128;
                cp_async16(sb + srow * 128 + ((u0 ^ (srow & 7)) << 4), src);
            }
            cp_commit();
        };

        load_chunk(0, 0);
        load_chunk(1, 1);

        for (int c = 0; c < nchunks; ++c) {
            cp_wait<1>();
            __syncthreads();                       // single sync per chunk

            if (c + 2 < nchunks) load_chunk(c + 2, (c + 2) % 3);
            else cp_commit();

            const uint32_t sb = sbase + (uint32_t)(c % 3) * STAGE;
            #pragma unroll
            for (int s = 0; s < 4; ++s) {          // four k16 steps per chunk
                uint32_t Aq[4][4];
                #pragma unroll
                for (int f = 0; f < 4; ++f) {
                    const int row = wm * 64 + f * 16 + ((g & 1) << 3) + l7;
                    const int ch = 2 * s + (g >> 1);
                    ldsm4(Aq[f], sb + row * 128 + ((ch ^ (row & 7)) << 4));
                }
                #pragma unroll
                for (int p = 0; p < 2; ++p) {      // two n16 groups
                    const int row = 128 + wn * 32 + p * 16 + ((g >> 1) << 3) + l7;
                    const int ch = 2 * s + (g & 1);
                    uint32_t Bq[4];
                    ldsm4(Bq, sb + row * 128 + ((ch ^ (row & 7)) << 4));
                    #pragma unroll
                    for (int f = 0; f < 4; ++f) {
                        mma16816(acc[f][2 * p],     Aq[f], Bq[0], Bq[1]);
                        mma16816(acc[f][2 * p + 1], Aq[f], Bq[2], Bq[3]);
                    }
                }
            }
        }

        // ---------------------------- epilogue -----------------------------
        #pragma unroll
        for (int f = 0; f < 4; ++f) {
            #pragma unroll
            for (int nf = 0; nf < 4; ++nf) {
                const long n = bn + wn * 32 + nf * 8 + tl * 2;
                #pragma unroll
                for (int h = 0; h < 2; ++h) {
                    const long m = bm + wm * 64 + f * 16 + tg + h * 8;
                    float v0 = acc[f][nf][2 * h + 0];
                    float v1 = acc[f][nf][2 * h + 1];
                    if (MODE == 0) {
                        v0 += bias0[n]; v1 += bias0[n + 1];
                        const int gate = (int)(n >> 10);
                        if (gate < 3) { v0 = sigm(v0); v1 = sigm(v1); }
                        else          { v0 = tanh_fast(v0); v1 = tanh_fast(v1); }
                        float* d = g_gates + (size_t)gate * BHsz
                                 + (size_t)m * 1024 + (n & 1023);
                        d[0] = v0; d[1] = v1;
                    } else if (MODE == 1) {
                        const float* ar = addend + (size_t)m * 1024;
                        v0 += bias0[n] + bias1[n] + ar[n];
                        v1 += bias0[n + 1] + bias1[n + 1] + ar[n + 1];
                        __half2 hv = __floats2half2_rn(v0, v1);
                        *reinterpret_cast<__half2*>(outh + (size_t)m * 1024 + n) = hv;
                    } else {
                        float* d = outf + (size_t)m * 1024 + n;
                        d[0] = v0 + bias0[n];
                        d[1] = v1 + bias0[n + 1];
                    }
                }
            }
        }
    }
}

// --------------------- vectorized conversion kernels -----------------------
__global__ void convA(const float* __restrict__ emb, const float* __restrict__ hid,
                      const float* __restrict__ ctx)
{
    const size_t i4 = (size_t)blockIdx.x * 256 + threadIdx.x;  // over B*1024/4
    const size_t m = i4 >> 8, c = (i4 & 255) * 4;
    float4 v;
    v = *reinterpret_cast<const float4*>(emb + m * 1024 + c);
    cvt_store4(g_Af + m * 3072 + c, v);
    v = *reinterpret_cast<const float4*>(hid + m * 1024 + c);
    cvt_store4(g_Af + m * 3072 + 1024 + c, v);
    v = *reinterpret_cast<const float4*>(ctx + m * 1024 + c);
    cvt_store4(g_Af + m * 3072 + 2048 + c, v);
    cvt_store4(g_Ahc + m * 2048 + 1024 + c, v);
}

__global__ void convW(const float* __restrict__ Wi, const float* __restrict__ Wf,
                      const float* __restrict__ Wo, const float* __restrict__ Wg)
{
    const int r = blockIdx.x;                 // 0..4095
    const int sel = r >> 10;
    const float* W = (sel == 0) ? Wi : (sel == 1) ? Wf : (sel == 2) ? Wo : Wg;
    const float* src = W + (size_t)(r & 1023) * 3072;
    __half* dst = g_Wf + (size_t)r * 3072;
    #pragma unroll
    for (int j = 0; j < 3; ++j) {
        const size_t c = (size_t)(threadIdx.x + j * 256) * 4;
        cvt_store4(dst + c, *reinterpret_cast<const float4*>(src + c));
    }
}

__global__ void convHC(const float* __restrict__ Wh, const float* __restrict__ Wc)
{
    const int r = blockIdx.x;                 // 0..1023
    __half* dst = g_Bhc + (size_t)r * 2048;
    #pragma unroll
    for (int j = 0; j < 2; ++j) {
        const size_t c = (size_t)(threadIdx.x + j * 256) * 4;
        const float* src = (c < 1024) ? (Wh + (size_t)r * 1024 + c)
                                      : (Wc + (size_t)r * 1024 + (c - 1024));
        cvt_store4(dst + c, *reinterpret_cast<const float4*>(src));
    }
}

__global__ void convP(const float* __restrict__ Wp)
{
    const size_t i4 = (size_t)blockIdx.x * 256 + threadIdx.x;  // 1M/4
    const size_t c = i4 * 4;
    cvt_store4(g_Wpf + c, *reinterpret_cast<const float4*>(Wp + c));
}

__global__ void convBias(const float* __restrict__ bi, const float* __restrict__ bf,
                         const float* __restrict__ bo, const float* __restrict__ bg)
{
    const int i = blockIdx.x * 256 + threadIdx.x;             // 4096
    const int sel = i >> 10, c = i & 1023;
    const float* b = (sel == 0) ? bi : (sel == 1) ? bf : (sel == 2) ? bo : bg;
    g_biascat[i] = b[c];
}

// cell = f*c_prev + i*g ; hidden = o*tanh(cell); fp16 hidden into Ahc
__global__ void cellhid_kernel(const float* __restrict__ cprev, float* __restrict__ out)
{
    const size_t i = ((size_t)blockIdx.x * blockDim.x + threadIdx.x) * 4;
    float4 gi = *(const float4*)&g_gates[i];
    float4 gf = *(const float4*)&g_gates[BHsz + i];
    float4 go = *(const float4*)&g_gates[2 * BHsz + i];
    float4 gg = *(const float4*)&g_gates[3 * BHsz + i];
    float4 cp = *(const float4*)&cprev[i];
    float4 c, h;
    c.x = gf.x * cp.x + gi.x * gg.x;  h.x = go.x * tanh_fast(c.x);
    c.y = gf.y * cp.y + gi.y * gg.y;  h.y = go.y * tanh_fast(c.y);
    c.z = gf.z * cp.z + gi.z * gg.z;  h.z = go.z * tanh_fast(c.z);
    c.w = gf.w * cp.w + gi.w * gg.w;  h.w = go.w * tanh_fast(c.w);
    *(float4*)&out[BHsz + i]     = h;
    *(float4*)&out[2 * BHsz + i] = c;
    const size_t m = i >> 10, c0 = i & 1023;
    cvt_store4(g_Ahc + m * 2048 + c0, h);
}

// ---------------------------------------------------------------------------
extern "C" void kernel_launch(void* const* d_in, const int* in_sizes, int n_in,
                              void* d_out, int out_size)
{
    const float* emb   = (const float*)d_in[0];
    const float* hid   = (const float*)d_in[1];
    const float* cprev = (const float*)d_in[2];
    const float* ctx   = (const float*)d_in[3];
    const float* Wi = (const float*)d_in[4];  const float* bi = (const float*)d_in[5];
    const float* Wf = (const float*)d_in[6];  const float* bf = (const float*)d_in[7];
    const float* Wo = (const float*)d_in[8];  const float* bo = (const float*)d_in[9];
    const float* Wg = (const float*)d_in[10]; const float* bg = (const float*)d_in[11];
    const float* Wc = (const float*)d_in[12]; const float* bc = (const float*)d_in[13];
    const float* Wh = (const float*)d_in[14]; const float* bh = (const float*)d_in[15];
    const float* Wp = (const float*)d_in[16]; const float* bp = (const float*)d_in[17];
    float* out = (float*)d_out;

    static bool init = false;
    static __half *Af, *Wf_, *Ahc, *Bhc, *Wpf, *res;
    static float *biascat;
    if (!init) {
        cudaGetSymbolAddress((void**)&Af, g_Af);
        cudaGetSymbolAddress((void**)&Wf_, g_Wf);
        cudaGetSymbolAddress((void**)&Ahc, g_Ahc);
        cudaGetSymbolAddress((void**)&Bhc, g_Bhc);
        cudaGetSymbolAddress((void**)&Wpf, g_Wpf);
        cudaGetSymbolAddress((void**)&res, g_res);
        cudaGetSymbolAddress((void**)&biascat, g_biascat);
        cudaFuncSetAttribute(gemm_ms<0>, cudaFuncAttributeMaxDynamicSharedMemorySize, 98304);
        cudaFuncSetAttribute(gemm_ms<1>, cudaFuncAttributeMaxDynamicSharedMemorySize, 98304);
        cudaFuncSetAttribute(gemm_ms<2>, cudaFuncAttributeMaxDynamicSharedMemorySize, 98304);
        init = true;
    }

    // 1) fp32 -> fp16 conversions
    convA<<<4096, 256>>>(emb, hid, ctx);
    convW<<<4096, 256>>>(Wi, Wf, Wo, Wg);
    convHC<<<1024, 256>>>(Wh, Wc);
    convP<<<1024, 256>>>(Wp);
    convBias<<<16, 256>>>(bi, bf, bo, bg);

    // 2) gates GEMM 4096x4096x3072 -> activated g_gates (persistent, 1024 tiles)
    gemm_ms<0><<<296, 256, 98304>>>(
        Af, Wf_, 3072, 3072, 48, 1024, biascat, nullptr, nullptr, nullptr, nullptr);

    // 3) cell/hidden elementwise (+ fp16 hidden into Ahc)
    cellhid_kernel<<<(int)(BHsz / 4 / 256), 256>>>(cprev, out);

    // 4) resid = emb + [hidden|ctx]@[Wh|Wc]^T + bh + bc -> g_res (fp16)
    gemm_ms<1><<<256, 256, 98304>>>(
        Ahc, Bhc, 2048, 2048, 32, 256, bh, bc, emb, nullptr, res);

    // 5) pred = resid@Wp^T + bp -> out[0..BH)
    gemm_ms<2><<<256, 256, 98304>>>(
        res, Wpf, 1024, 1024, 16, 256, bp, nullptr, nullptr, out, nullptr);
}